// round 4
// baseline (speedup 1.0000x reference)
#include <cuda_runtime.h>
#include <math.h>
#include <stdint.h>

// Problem constants (fixed shapes in dataset; runtime values derived from in_sizes)
#define NMAX   100000
#define EMAX   1600000
#define IN_F   256
#define HID    128

// ---------------- device scratch (static; no allocations allowed) -------------
// All atomics target these __device__ globals (GPU vidmem). d_out only ever
// receives plain stores (f32 RED atomics into the harness buffer trap on GB300).
__device__ __align__(16) float g_tgt_hl[(size_t)NMAX * HID];   // 51.2 MB
__device__ __align__(16) float g_accum[(size_t)NMAX * HID];    // 51.2 MB
__device__ __align__(16) float g_sscore[NMAX];
__device__ __align__(16) float g_tscore[NMAX];
__device__ __align__(16) float g_denom[NMAX];
__device__ __align__(16) float g_eexp[EMAX];
__device__ __align__(16) float g_wsproj[IN_F];
__device__ __align__(16) float g_wtproj[IN_F];
__device__ float g_cs;     // b_lin . w_s
__device__ float g_ct;     // b_lin . w_t + att_b
__device__ int   g_idx64;  // 1 if edge_list is int64, 0 if int32

// ---------------- edge index accessor (dtype-agnostic) ------------------------
__device__ __forceinline__ int edge_at(const void* e, int is64, long long pos) {
    if (is64) return (int)((const long long*)e)[pos];
    return ((const int*)e)[pos];
}

// ---------------- -1: detect edge dtype ---------------------------------------
// If int64 (values < 2^31), every odd 32-bit word is a zero high-word.
// For int32 data the odd words are random node indices; all-zero is impossible.
__global__ void detect_kernel(const int* __restrict__ edges_i32) {
    int nz = 0;
    for (int i = 1; i < 256; i += 2) nz += (edges_i32[i] != 0);
    g_idx64 = (nz == 0) ? 1 : 0;
}

// ---------------- 0: project attention vectors through W ----------------------
// ws_proj[k] = sum_h W[h,k]*att_w[h];  wt_proj[k] = sum_h W[h,k]*att_w[HID+h]
__global__ void proj_kernel(const float* __restrict__ W,
                            const float* __restrict__ b_lin,
                            const float* __restrict__ att_w,
                            const float* __restrict__ att_b) {
    int k = threadIdx.x;  // 0..255
    float s = 0.f, t = 0.f;
#pragma unroll 8
    for (int h = 0; h < HID; ++h) {
        float w = W[h * IN_F + k];
        s += w * att_w[h];
        t += w * att_w[HID + h];
    }
    g_wsproj[k] = s;
    g_wtproj[k] = t;
    if (k == 0) {
        float cs = 0.f, ct = 0.f;
        for (int h = 0; h < HID; ++h) {
            cs += b_lin[h] * att_w[h];
            ct += b_lin[h] * att_w[HID + h];
        }
        g_cs = cs;
        g_ct = ct + att_b[0];
    }
}

// ---------------- 1: init accumulator with bias, zero denominators ------------
__global__ void init_kernel(const float* __restrict__ bias, int nsrc) {
    int i = blockIdx.x * blockDim.x + threadIdx.x;
    int total = nsrc * HID;
    if (i < total) g_accum[i] = bias[i & (HID - 1)];
    if (i < nsrc) g_denom[i] = 0.f;
}

// ---------------- 2: per-node scores (warp per node) --------------------------
__global__ void score_kernel(const float* __restrict__ src,
                             const float* __restrict__ tgt,
                             int nsrc, int ntgt) {
    int gtid = blockIdx.x * blockDim.x + threadIdx.x;
    int wid = gtid >> 5;
    int lane = gtid & 31;
    int total = nsrc + ntgt;
    if (wid >= total) return;
    bool is_src = wid < nsrc;
    int node = is_src ? wid : (wid - nsrc);
    const float* row = (is_src ? src : tgt) + (size_t)node * IN_F;
    const float* proj = is_src ? g_wsproj : g_wtproj;

    float4 a = ((const float4*)row)[lane];
    float4 b = ((const float4*)row)[lane + 32];
    float4 pa = ((const float4*)proj)[lane];
    float4 pb = ((const float4*)proj)[lane + 32];
    float d = a.x * pa.x + a.y * pa.y + a.z * pa.z + a.w * pa.w
            + b.x * pb.x + b.y * pb.y + b.z * pb.z + b.w * pb.w;
#pragma unroll
    for (int o = 16; o; o >>= 1) d += __shfl_down_sync(0xFFFFFFFFu, d, o);
    if (lane == 0) {
        if (is_src) g_sscore[node] = d + g_cs;
        else        g_tscore[node] = d + g_ct;
    }
}

// ---------------- 3: tgt_hl = target_h @ W^T + b_lin (SGEMM) -------------------
// BM=64 rows, BN=128 cols, BK=16. 256 threads; thread computes 8 rows x 4 cols.
__global__ void gemm_kernel(const float* __restrict__ A,   // [M, 256]
                            const float* __restrict__ Wm,  // [128, 256]
                            const float* __restrict__ b_lin,
                            int M) {
    __shared__ float As[16][65];    // padded: conflict-free transposed stores
    __shared__ float Bs[16][128];

    int tid = threadIdx.x;
    int tx = tid & 31;   // lane = col group (4 cols)
    int ty = tid >> 5;   // warp = row group (8 rows)
    int row0 = blockIdx.x * 64;

    float acc[8][4];
    float bl[4];
#pragma unroll
    for (int j = 0; j < 4; ++j) bl[j] = b_lin[tx * 4 + j];
#pragma unroll
    for (int i = 0; i < 8; ++i)
#pragma unroll
        for (int j = 0; j < 4; ++j) acc[i][j] = bl[j];

    int ar = tid >> 2;          // 0..63
    int ak = (tid & 3) * 4;     // 0,4,8,12

    for (int k0 = 0; k0 < IN_F; k0 += 16) {
        float4 av = make_float4(0.f, 0.f, 0.f, 0.f);
        int grow = row0 + ar;
        if (grow < M) av = *(const float4*)(A + (size_t)grow * IN_F + k0 + ak);
        As[ak + 0][ar] = av.x; As[ak + 1][ar] = av.y;
        As[ak + 2][ar] = av.z; As[ak + 3][ar] = av.w;
        float4 bv0 = *(const float4*)(Wm + (size_t)ar * IN_F + k0 + ak);
        float4 bv1 = *(const float4*)(Wm + (size_t)(ar + 64) * IN_F + k0 + ak);
        Bs[ak + 0][ar] = bv0.x; Bs[ak + 1][ar] = bv0.y;
        Bs[ak + 2][ar] = bv0.z; Bs[ak + 3][ar] = bv0.w;
        Bs[ak + 0][ar + 64] = bv1.x; Bs[ak + 1][ar + 64] = bv1.y;
        Bs[ak + 2][ar + 64] = bv1.z; Bs[ak + 3][ar + 64] = bv1.w;
        __syncthreads();

#pragma unroll
        for (int k = 0; k < 16; ++k) {
            float rb[4];
#pragma unroll
            for (int j = 0; j < 4; ++j) rb[j] = Bs[k][tx * 4 + j];
#pragma unroll
            for (int i = 0; i < 8; ++i) {
                float ra = As[k][ty * 8 + i];
#pragma unroll
                for (int j = 0; j < 4; ++j) acc[i][j] += ra * rb[j];
            }
        }
        __syncthreads();
    }

#pragma unroll
    for (int i = 0; i < 8; ++i) {
        int grow = row0 + ty * 8 + i;
        if (grow < M) {
            float4 v = make_float4(acc[i][0], acc[i][1], acc[i][2], acc[i][3]);
            *(float4*)(g_tgt_hl + (size_t)grow * HID + tx * 4) = v;
        }
    }
}

// ---------------- 4: edge pass 1: e_exp + segment denominator -----------------
// e in [-1,1] (tanh): segment-max is unnecessary for stability and cancels
// mathematically in att = exp(e-m)/sum(exp(e'-m)).
__global__ void edge1_kernel(const void* __restrict__ edges, int E) {
    int i = blockIdx.x * blockDim.x + threadIdx.x;
    if (i >= E) return;
    int is64 = g_idx64;
    int si = edge_at(edges, is64, i);
    int ti = edge_at(edges, is64, (long long)E + i);
    float e = tanhf(g_sscore[si] + g_tscore[ti]);  // offsets folded into scores
    float ex = __expf(e);
    g_eexp[i] = ex;
    atomicAdd(&g_denom[si], ex);
}

// ---------------- 5: edge pass 2: weighted scatter (warp per edge) ------------
__global__ void edge2_kernel(const void* __restrict__ edges, int E) {
    int gtid = blockIdx.x * blockDim.x + threadIdx.x;
    int wid = gtid >> 5;
    if (wid >= E) return;
    int lane = gtid & 31;
    int is64 = g_idx64;
    int si = edge_at(edges, is64, wid);
    int ti = edge_at(edges, is64, (long long)E + wid);
    float att = g_eexp[wid] / g_denom[si];

    float4 v = ((const float4*)(g_tgt_hl + (size_t)ti * HID))[lane];
    float* dst = g_accum + (size_t)si * HID + lane * 4;
    atomicAdd(dst + 0, att * v.x);
    atomicAdd(dst + 1, att * v.y);
    atomicAdd(dst + 2, att * v.z);
    atomicAdd(dst + 3, att * v.w);
}

// ---------------- 6: copy accumulator to output (plain stores only) -----------
__global__ void copy_kernel(float* __restrict__ out, int total4) {
    int i = blockIdx.x * blockDim.x + threadIdx.x;
    if (i < total4) ((float4*)out)[i] = ((const float4*)g_accum)[i];
}

// ---------------- launch -------------------------------------------------------
extern "C" void kernel_launch(void* const* d_in, const int* in_sizes, int n_in,
                              void* d_out, int out_size) {
    const float* source_h   = (const float*)d_in[0];
    const float* target_h   = (const float*)d_in[1];
    const void*  edges      = d_in[2];
    const float* W          = (const float*)d_in[3];
    const float* b_lin      = (const float*)d_in[4];
    const float* att_w      = (const float*)d_in[5];
    const float* att_b      = (const float*)d_in[6];
    const float* bias       = (const float*)d_in[7];

    int nsrc = in_sizes[0] / IN_F;
    int ntgt = in_sizes[1] / IN_F;
    int E    = in_sizes[2] / 2;
    float* out = (float*)d_out;

    detect_kernel<<<1, 1>>>((const int*)edges);
    proj_kernel<<<1, 256>>>(W, b_lin, att_w, att_b);
    init_kernel<<<(nsrc * HID + 255) / 256, 256>>>(bias, nsrc);
    score_kernel<<<(int)(((long long)(nsrc + ntgt) * 32 + 255) / 256), 256>>>(
        source_h, target_h, nsrc, ntgt);
    gemm_kernel<<<(ntgt + 63) / 64, 256>>>(target_h, W, b_lin, ntgt);
    edge1_kernel<<<(E + 255) / 256, 256>>>(edges, E);
    edge2_kernel<<<(int)(((long long)E * 32 + 255) / 256), 256>>>(edges, E);
    copy_kernel<<<(nsrc * HID / 4 + 255) / 256, 256>>>(out, nsrc * HID / 4);
}

// round 5
// speedup vs baseline: 1.8564x; 1.8564x over previous
#include <cuda_runtime.h>
#include <math.h>
#include <stdint.h>

#define NMAX   100000
#define EMAX   1600000
#define IN_F   256
#define HID    128

// ---------------- device scratch (static; no allocations allowed) -------------
// Atomics only ever target these __device__ globals (GPU vidmem). d_out gets
// plain stores only (RED atomics into the harness buffer trap on GB300).
__device__ __align__(16) float g_tgt_hl[(size_t)NMAX * HID];   // 51.2 MB
__device__ __align__(16) float g_sscore[NMAX];
__device__ __align__(16) float g_tscore[NMAX];
__device__ __align__(16) float g_denom[NMAX];
__device__ __align__(16) float g_eexp[EMAX];
__device__ __align__(16) unsigned long long g_srec[EMAX];      // packed (att, ti)
__device__ int g_deg[NMAX];
__device__ int g_base[NMAX];
__device__ int g_cursor[NMAX];
__device__ int g_bsum[128];
__device__ __align__(16) float g_wsproj[IN_F];
__device__ __align__(16) float g_wtproj[IN_F];
__device__ float g_cs;     // b_lin . w_s
__device__ float g_ct;     // b_lin . w_t + att_b
__device__ int   g_idx64;  // 1 if edge_list is int64, 0 if int32

// ---------------- edge index accessor (dtype-agnostic) ------------------------
__device__ __forceinline__ int edge_at(const void* e, int is64, long long pos) {
    if (is64) return (int)((const long long*)e)[pos];
    return ((const int*)e)[pos];
}

// If int64 (values < 2^31), every odd 32-bit word is a zero high-word.
__global__ void detect_kernel(const int* __restrict__ edges_i32) {
    int nz = 0;
    for (int i = 1; i < 256; i += 2) nz += (edges_i32[i] != 0);
    g_idx64 = (nz == 0) ? 1 : 0;
}

// ---------------- 0: project attention vectors through W ----------------------
__global__ void proj_kernel(const float* __restrict__ W,
                            const float* __restrict__ b_lin,
                            const float* __restrict__ att_w,
                            const float* __restrict__ att_b) {
    int k = threadIdx.x;  // 0..255
    float s = 0.f, t = 0.f;
#pragma unroll 8
    for (int h = 0; h < HID; ++h) {
        float w = W[h * IN_F + k];
        s += w * att_w[h];
        t += w * att_w[HID + h];
    }
    g_wsproj[k] = s;
    g_wtproj[k] = t;
    if (k == 0) {
        float cs = 0.f, ct = 0.f;
        for (int h = 0; h < HID; ++h) {
            cs += b_lin[h] * att_w[h];
            ct += b_lin[h] * att_w[HID + h];
        }
        g_cs = cs;
        g_ct = ct + att_b[0];
    }
}

// ---------------- 1: zero per-node counters ------------------------------------
__global__ void zero_kernel(int nsrc) {
    int i = blockIdx.x * blockDim.x + threadIdx.x;
    if (i < nsrc) { g_denom[i] = 0.f; g_deg[i] = 0; }
}

// ---------------- 2: per-node scores (warp per node) --------------------------
__global__ void score_kernel(const float* __restrict__ src,
                             const float* __restrict__ tgt,
                             int nsrc, int ntgt) {
    int gtid = blockIdx.x * blockDim.x + threadIdx.x;
    int wid = gtid >> 5;
    int lane = gtid & 31;
    int total = nsrc + ntgt;
    if (wid >= total) return;
    bool is_src = wid < nsrc;
    int node = is_src ? wid : (wid - nsrc);
    const float* row = (is_src ? src : tgt) + (size_t)node * IN_F;
    const float* proj = is_src ? g_wsproj : g_wtproj;

    float4 a = ((const float4*)row)[lane];
    float4 b = ((const float4*)row)[lane + 32];
    float4 pa = ((const float4*)proj)[lane];
    float4 pb = ((const float4*)proj)[lane + 32];
    float d = a.x * pa.x + a.y * pa.y + a.z * pa.z + a.w * pa.w
            + b.x * pb.x + b.y * pb.y + b.z * pb.z + b.w * pb.w;
#pragma unroll
    for (int o = 16; o; o >>= 1) d += __shfl_down_sync(0xFFFFFFFFu, d, o);
    if (lane == 0) {
        if (is_src) g_sscore[node] = d + g_cs;
        else        g_tscore[node] = d + g_ct;
    }
}

// ---------------- 3: tgt_hl = target_h @ W^T + b_lin (SGEMM) -------------------
// BM=128, BN=128, BK=16, 256 threads; each thread computes 8 rows x 8 cols.
__global__ void gemm_kernel(const float* __restrict__ A,   // [M, 256]
                            const float* __restrict__ Wm,  // [128, 256]
                            const float* __restrict__ b_lin,
                            int M) {
    __shared__ float As[16][132];   // padded
    __shared__ float Bs[16][128];

    int tid = threadIdx.x;
    int tx = tid & 15;   // col group: 8 cols
    int ty = tid >> 4;   // row group: 8 rows (0..15)
    int row0 = blockIdx.x * 128;

    float acc[8][8];
#pragma unroll
    for (int j = 0; j < 8; ++j) {
        float bl = b_lin[tx * 8 + j];
#pragma unroll
        for (int i = 0; i < 8; ++i) acc[i][j] = bl;
    }

    int lr = tid >> 1;            // 0..127 : row / W out-col
    int lk0 = (tid & 1) * 4;      // 0 or 4

    for (int k0 = 0; k0 < IN_F; k0 += 16) {
        // A tile: 128 rows x 16 k, each thread loads 2 float4
#pragma unroll
        for (int h = 0; h < 2; ++h) {
            int kk = lk0 + h * 8;   // 0,8 or 4,12
            float4 av = make_float4(0.f, 0.f, 0.f, 0.f);
            int grow = row0 + lr;
            if (grow < M) av = *(const float4*)(A + (size_t)grow * IN_F + k0 + kk);
            As[kk + 0][lr] = av.x; As[kk + 1][lr] = av.y;
            As[kk + 2][lr] = av.z; As[kk + 3][lr] = av.w;
            float4 bv = *(const float4*)(Wm + (size_t)lr * IN_F + k0 + kk);
            Bs[kk + 0][lr] = bv.x; Bs[kk + 1][lr] = bv.y;
            Bs[kk + 2][lr] = bv.z; Bs[kk + 3][lr] = bv.w;
        }
        __syncthreads();

#pragma unroll
        for (int k = 0; k < 16; ++k) {
            float ra[8], rb[8];
#pragma unroll
            for (int i = 0; i < 8; ++i) ra[i] = As[k][ty * 8 + i];
#pragma unroll
            for (int j = 0; j < 8; ++j) rb[j] = Bs[k][tx * 8 + j];
#pragma unroll
            for (int i = 0; i < 8; ++i)
#pragma unroll
                for (int j = 0; j < 8; ++j) acc[i][j] += ra[i] * rb[j];
        }
        __syncthreads();
    }

#pragma unroll
    for (int i = 0; i < 8; ++i) {
        int grow = row0 + ty * 8 + i;
        if (grow < M) {
            *(float4*)(g_tgt_hl + (size_t)grow * HID + tx * 8) =
                make_float4(acc[i][0], acc[i][1], acc[i][2], acc[i][3]);
            *(float4*)(g_tgt_hl + (size_t)grow * HID + tx * 8 + 4) =
                make_float4(acc[i][4], acc[i][5], acc[i][6], acc[i][7]);
        }
    }
}

// ---------------- 4: edge pass 1: e_exp + denom + degree histogram -------------
// e in [-1,1] (tanh): segment-max cancels mathematically in the softmax.
__global__ void edge1_kernel(const void* __restrict__ edges, int E) {
    int i = blockIdx.x * blockDim.x + threadIdx.x;
    if (i >= E) return;
    int is64 = g_idx64;
    int si = edge_at(edges, is64, i);
    int ti = edge_at(edges, is64, (long long)E + i);
    float e = tanhf(g_sscore[si] + g_tscore[ti]);
    float ex = __expf(e);
    g_eexp[i] = ex;
    atomicAdd(&g_denom[si], ex);
    atomicAdd(&g_deg[si], 1);
}

// ---------------- 5: exclusive scan of degrees (3 kernels) ---------------------
__global__ void scan1_kernel(int n) {      // grid: nb x 1024 threads
    __shared__ int s[1024];
    int i = blockIdx.x * 1024 + threadIdx.x;
    int v = (i < n) ? g_deg[i] : 0;
    s[threadIdx.x] = v;
    __syncthreads();
#pragma unroll
    for (int o = 1; o < 1024; o <<= 1) {
        int t = (threadIdx.x >= o) ? s[threadIdx.x - o] : 0;
        __syncthreads();
        s[threadIdx.x] += t;
        __syncthreads();
    }
    if (i < n) g_base[i] = s[threadIdx.x] - v;   // exclusive within block
    if (threadIdx.x == 1023) g_bsum[blockIdx.x] = s[1023];
}
__global__ void scan2_kernel(int nb) {     // 1 block x 128 threads, nb <= 128
    __shared__ int s[128];
    int v = (threadIdx.x < nb) ? g_bsum[threadIdx.x] : 0;
    s[threadIdx.x] = v;
    __syncthreads();
#pragma unroll
    for (int o = 1; o < 128; o <<= 1) {
        int t = (threadIdx.x >= o) ? s[threadIdx.x - o] : 0;
        __syncthreads();
        s[threadIdx.x] += t;
        __syncthreads();
    }
    if (threadIdx.x < nb) g_bsum[threadIdx.x] = s[threadIdx.x] - v;  // exclusive
}
__global__ void scan3_kernel(int n) {
    int i = blockIdx.x * blockDim.x + threadIdx.x;
    if (i < n) {
        int b = g_base[i] + g_bsum[i >> 10];
        g_base[i] = b;
        g_cursor[i] = b;
    }
}

// ---------------- 6: scatter packed (att, ti) records sorted by si -------------
__global__ void scatter_kernel(const void* __restrict__ edges, int E) {
    int i = blockIdx.x * blockDim.x + threadIdx.x;
    if (i >= E) return;
    int is64 = g_idx64;
    int si = edge_at(edges, is64, i);
    int ti = edge_at(edges, is64, (long long)E + i);
    float att = g_eexp[i] / g_denom[si];
    int pos = atomicAdd(&g_cursor[si], 1);
    g_srec[pos] = ((unsigned long long)(unsigned)__float_as_int(att) << 32)
                | (unsigned)ti;
}

// ---------------- 7: aggregate (warp per source node, registers, no atomics) ---
__global__ void agg_kernel(float* __restrict__ out,
                           const float* __restrict__ bias, int nsrc) {
    int wid = (blockIdx.x * blockDim.x + threadIdx.x) >> 5;
    int lane = threadIdx.x & 31;
    if (wid >= nsrc) return;
    int start = g_base[wid];
    int deg   = g_deg[wid];

    float4 acc = ((const float4*)bias)[lane];
    for (int p = start; p < start + deg; ++p) {
        unsigned long long r = g_srec[p];            // uniform across warp
        int ti = (int)(unsigned)(r & 0xffffffffu);
        float att = __int_as_float((int)(r >> 32));
        float4 v = ((const float4*)(g_tgt_hl + (size_t)ti * HID))[lane];
        acc.x += att * v.x; acc.y += att * v.y;
        acc.z += att * v.z; acc.w += att * v.w;
    }
    ((float4*)(out + (size_t)wid * HID))[lane] = acc;
}

// ---------------- launch -------------------------------------------------------
extern "C" void kernel_launch(void* const* d_in, const int* in_sizes, int n_in,
                              void* d_out, int out_size) {
    const float* source_h   = (const float*)d_in[0];
    const float* target_h   = (const float*)d_in[1];
    const void*  edges      = d_in[2];
    const float* W          = (const float*)d_in[3];
    const float* b_lin      = (const float*)d_in[4];
    const float* att_w      = (const float*)d_in[5];
    const float* att_b      = (const float*)d_in[6];
    const float* bias       = (const float*)d_in[7];

    int nsrc = in_sizes[0] / IN_F;
    int ntgt = in_sizes[1] / IN_F;
    int E    = in_sizes[2] / 2;
    float* out = (float*)d_out;
    int nb = (nsrc + 1023) / 1024;

    detect_kernel<<<1, 1>>>((const int*)edges);
    proj_kernel<<<1, 256>>>(W, b_lin, att_w, att_b);
    zero_kernel<<<(nsrc + 255) / 256, 256>>>(nsrc);
    score_kernel<<<(int)(((long long)(nsrc + ntgt) * 32 + 255) / 256), 256>>>(
        source_h, target_h, nsrc, ntgt);
    gemm_kernel<<<(ntgt + 127) / 128, 256>>>(target_h, W, b_lin, ntgt);
    edge1_kernel<<<(E + 255) / 256, 256>>>(edges, E);
    scan1_kernel<<<nb, 1024>>>(nsrc);
    scan2_kernel<<<1, 128>>>(nb);
    scan3_kernel<<<(nsrc + 255) / 256, 256>>>(nsrc);
    scatter_kernel<<<(E + 255) / 256, 256>>>(edges, E);
    agg_kernel<<<(int)(((long long)nsrc * 32 + 255) / 256), 256>>>(out, bias, nsrc);
}

// round 7
// speedup vs baseline: 2.4727x; 1.3320x over previous
#include <cuda_runtime.h>
#include <cuda_bf16.h>
#include <mma.h>
#include <math.h>
#include <stdint.h>

using namespace nvcuda;

#define NMAX   100000
#define EMAX   1600000
#define IN_F   256
#define HID    128

// ---------------- device scratch (static; no allocations allowed) -------------
// Padded by 128 rows: boundary GEMM tile stores unguarded into the pad.
__device__ __align__(16) float g_tgt_hl[(size_t)(NMAX + 128) * HID];
__device__ __align__(16) float g_sscore[NMAX];
__device__ __align__(16) float g_tscore[NMAX];
__device__ __align__(16) float g_denom[NMAX];
__device__ __align__(16) float g_eexp[EMAX];
__device__ __align__(16) unsigned long long g_srec[EMAX];      // packed (att, ti)
__device__ int g_deg[NMAX];
__device__ int g_base[NMAX];
__device__ int g_cursor[NMAX];
__device__ int g_bsum[128];
__device__ __align__(16) float g_wsproj[IN_F];
__device__ __align__(16) float g_wtproj[IN_F];
__device__ float g_cs;
__device__ float g_ct;
__device__ int   g_idx64;

// ---------------- edge index accessor ------------------------------------------
__device__ __forceinline__ int edge_at(const void* e, int is64, long long pos) {
    if (is64) return (int)((const long long*)e)[pos];
    return ((const int*)e)[pos];
}
__global__ void detect_kernel(const int* __restrict__ edges_i32) {
    int nz = 0;
    for (int i = 1; i < 256; i += 2) nz += (edges_i32[i] != 0);
    g_idx64 = (nz == 0) ? 1 : 0;
}

// ---------------- proj ----------------------------------------------------------
__global__ void proj_kernel(const float* __restrict__ W,
                            const float* __restrict__ b_lin,
                            const float* __restrict__ att_w,
                            const float* __restrict__ att_b) {
    int k = threadIdx.x;
    float s = 0.f, t = 0.f;
#pragma unroll 8
    for (int h = 0; h < HID; ++h) {
        float w = W[h * IN_F + k];
        s += w * att_w[h];
        t += w * att_w[HID + h];
    }
    g_wsproj[k] = s;
    g_wtproj[k] = t;
    if (k == 0) {
        float cs = 0.f, ct = 0.f;
        for (int h = 0; h < HID; ++h) {
            cs += b_lin[h] * att_w[h];
            ct += b_lin[h] * att_w[HID + h];
        }
        g_cs = cs;
        g_ct = ct + att_b[0];
    }
}

__global__ void zero_kernel(int nsrc) {
    int i = blockIdx.x * blockDim.x + threadIdx.x;
    if (i < nsrc) { g_denom[i] = 0.f; g_deg[i] = 0; }
}

// ---------------- per-node scores (warp per node) -------------------------------
__global__ void score_kernel(const float* __restrict__ src,
                             const float* __restrict__ tgt,
                             int nsrc, int ntgt) {
    int gtid = blockIdx.x * blockDim.x + threadIdx.x;
    int wid = gtid >> 5;
    int lane = gtid & 31;
    int total = nsrc + ntgt;
    if (wid >= total) return;
    bool is_src = wid < nsrc;
    int node = is_src ? wid : (wid - nsrc);
    const float* row = (is_src ? src : tgt) + (size_t)node * IN_F;
    const float* proj = is_src ? g_wsproj : g_wtproj;

    float4 a = ((const float4*)row)[lane];
    float4 b = ((const float4*)row)[lane + 32];
    float4 pa = ((const float4*)proj)[lane];
    float4 pb = ((const float4*)proj)[lane + 32];
    float d = a.x * pa.x + a.y * pa.y + a.z * pa.z + a.w * pa.w
            + b.x * pb.x + b.y * pb.y + b.z * pb.z + b.w * pb.w;
#pragma unroll
    for (int o = 16; o; o >>= 1) d += __shfl_down_sync(0xFFFFFFFFu, d, o);
    if (lane == 0) {
        if (is_src) g_sscore[node] = d + g_cs;
        else        g_tscore[node] = d + g_ct;
    }
}

// ================= wmma split-bf16 GEMM =========================================
// g_tgt_hl[M,128] = A[M,256] @ W^T  (bias folded into agg via sum(att)=1)
// D = Ahi*Whi + Ahi*Wlo + Alo*Whi  (bf16 hi/lo split; lo*lo term negligible)
#define BK  32
#define LDT 40   // padded bf16 row pitch (80B, 16B-aligned for ldmatrix)

__global__ void __launch_bounds__(256)
mma_gemm_kernel(const float* __restrict__ A, const float* __restrict__ Wm, int M) {
    __shared__ __nv_bfloat16 sAh[128 * LDT];
    __shared__ __nv_bfloat16 sAl[128 * LDT];
    __shared__ __nv_bfloat16 sWh[128 * LDT];
    __shared__ __nv_bfloat16 sWl[128 * LDT];

    int tid = threadIdx.x;
    int warp = tid >> 5;
    int wm = warp & 1;        // 2 warps in M: 64 rows each
    int wn = warp >> 1;       // 4 warps in N: 32 cols each
    int row0 = blockIdx.x * 128;

    wmma::fragment<wmma::accumulator, 16, 16, 16, float> acc[4][2];
#pragma unroll
    for (int i = 0; i < 4; ++i)
#pragma unroll
        for (int j = 0; j < 2; ++j) wmma::fill_fragment(acc[i][j], 0.f);

    for (int k0 = 0; k0 < IN_F; k0 += BK) {
#pragma unroll
        for (int q = 0; q < 4; ++q) {
            int idx = tid + q * 256;         // 0..1023
            int r = idx >> 3;                // 0..127
            int c = (idx & 7) * 4;           // 0..28
            // A row (guarded)
            float4 v = make_float4(0.f, 0.f, 0.f, 0.f);
            int grow = row0 + r;
            if (grow < M) v = *(const float4*)(A + (size_t)grow * IN_F + k0 + c);
            __nv_bfloat162 h01 = __floats2bfloat162_rn(v.x, v.y);
            __nv_bfloat162 h23 = __floats2bfloat162_rn(v.z, v.w);
            __nv_bfloat162 l01 = __floats2bfloat162_rn(
                v.x - __bfloat162float(h01.x), v.y - __bfloat162float(h01.y));
            __nv_bfloat162 l23 = __floats2bfloat162_rn(
                v.z - __bfloat162float(h23.x), v.w - __bfloat162float(h23.y));
            *(uint2*)&sAh[r * LDT + c] =
                make_uint2(*(uint32_t*)&h01, *(uint32_t*)&h23);
            *(uint2*)&sAl[r * LDT + c] =
                make_uint2(*(uint32_t*)&l01, *(uint32_t*)&l23);
            // W row (always valid; r = output col)
            float4 w = *(const float4*)(Wm + (size_t)r * IN_F + k0 + c);
            __nv_bfloat162 wh01 = __floats2bfloat162_rn(w.x, w.y);
            __nv_bfloat162 wh23 = __floats2bfloat162_rn(w.z, w.w);
            __nv_bfloat162 wl01 = __floats2bfloat162_rn(
                w.x - __bfloat162float(wh01.x), w.y - __bfloat162float(wh01.y));
            __nv_bfloat162 wl23 = __floats2bfloat162_rn(
                w.z - __bfloat162float(wh23.x), w.w - __bfloat162float(wh23.y));
            *(uint2*)&sWh[r * LDT + c] =
                make_uint2(*(uint32_t*)&wh01, *(uint32_t*)&wh23);
            *(uint2*)&sWl[r * LDT + c] =
                make_uint2(*(uint32_t*)&wl01, *(uint32_t*)&wl23);
        }
        __syncthreads();

#pragma unroll
        for (int kf = 0; kf < 2; ++kf) {
            wmma::fragment<wmma::matrix_a, 16, 16, 16, __nv_bfloat16,
                           wmma::row_major> ah[4], al[4];
            wmma::fragment<wmma::matrix_b, 16, 16, 16, __nv_bfloat16,
                           wmma::col_major> bh[2], bl[2];
#pragma unroll
            for (int i = 0; i < 4; ++i) {
                int r = wm * 64 + i * 16;
                wmma::load_matrix_sync(ah[i], sAh + r * LDT + kf * 16, LDT);
                wmma::load_matrix_sync(al[i], sAl + r * LDT + kf * 16, LDT);
            }
#pragma unroll
            for (int j = 0; j < 2; ++j) {
                int n = wn * 32 + j * 16;
                wmma::load_matrix_sync(bh[j], sWh + n * LDT + kf * 16, LDT);
                wmma::load_matrix_sync(bl[j], sWl + n * LDT + kf * 16, LDT);
            }
#pragma unroll
            for (int i = 0; i < 4; ++i)
#pragma unroll
                for (int j = 0; j < 2; ++j) {
                    wmma::mma_sync(acc[i][j], ah[i], bh[j], acc[i][j]);
                    wmma::mma_sync(acc[i][j], ah[i], bl[j], acc[i][j]);
                    wmma::mma_sync(acc[i][j], al[i], bh[j], acc[i][j]);
                }
        }
        __syncthreads();
    }

#pragma unroll
    for (int i = 0; i < 4; ++i)
#pragma unroll
        for (int j = 0; j < 2; ++j) {
            size_t r = (size_t)row0 + wm * 64 + i * 16;   // pad covers overrun
            int n = wn * 32 + j * 16;
            wmma::store_matrix_sync(g_tgt_hl + r * HID + n, acc[i][j], HID,
                                    wmma::mem_row_major);
        }
}

// ---------------- edge pass 1: e_exp + denom + degree histogram -----------------
// e in [-1,1] (tanh): segment-max cancels mathematically in the softmax.
__global__ void edge1_kernel(const void* __restrict__ edges, int E) {
    int i = blockIdx.x * blockDim.x + threadIdx.x;
    if (i >= E) return;
    int is64 = g_idx64;
    int si = edge_at(edges, is64, i);
    int ti = edge_at(edges, is64, (long long)E + i);
    float e = tanhf(g_sscore[si] + g_tscore[ti]);
    float ex = __expf(e);
    g_eexp[i] = ex;
    atomicAdd(&g_denom[si], ex);
    atomicAdd(&g_deg[si], 1);
}

// ---------------- exclusive scan of degrees --------------------------------------
__global__ void scan1_kernel(int n) {
    __shared__ int s[1024];
    int i = blockIdx.x * 1024 + threadIdx.x;
    int v = (i < n) ? g_deg[i] : 0;
    s[threadIdx.x] = v;
    __syncthreads();
#pragma unroll
    for (int o = 1; o < 1024; o <<= 1) {
        int t = (threadIdx.x >= o) ? s[threadIdx.x - o] : 0;
        __syncthreads();
        s[threadIdx.x] += t;
        __syncthreads();
    }
    if (i < n) g_base[i] = s[threadIdx.x] - v;
    if (threadIdx.x == 1023) g_bsum[blockIdx.x] = s[1023];
}
__global__ void scan2_kernel(int nb) {
    __shared__ int s[128];
    int v = (threadIdx.x < nb) ? g_bsum[threadIdx.x] : 0;
    s[threadIdx.x] = v;
    __syncthreads();
#pragma unroll
    for (int o = 1; o < 128; o <<= 1) {
        int t = (threadIdx.x >= o) ? s[threadIdx.x - o] : 0;
        __syncthreads();
        s[threadIdx.x] += t;
        __syncthreads();
    }
    if (threadIdx.x < nb) g_bsum[threadIdx.x] = s[threadIdx.x] - v;
}
__global__ void scan3_kernel(int n) {
    int i = blockIdx.x * blockDim.x + threadIdx.x;
    if (i < n) {
        int b = g_base[i] + g_bsum[i >> 10];
        g_base[i] = b;
        g_cursor[i] = b;
    }
}

// ---------------- scatter packed (att, ti) records sorted by si ------------------
__global__ void scatter_kernel(const void* __restrict__ edges, int E) {
    int i = blockIdx.x * blockDim.x + threadIdx.x;
    if (i >= E) return;
    int is64 = g_idx64;
    int si = edge_at(edges, is64, i);
    int ti = edge_at(edges, is64, (long long)E + i);
    float att = g_eexp[i] / g_denom[si];
    int pos = atomicAdd(&g_cursor[si], 1);
    g_srec[pos] = ((unsigned long long)(unsigned)__float_as_int(att) << 32)
                | (unsigned)ti;
}

// ---------------- aggregate (warp per source node) --------------------------------
// tgt_hl excludes b_lin; since sum(att)=1 per node, add b_lin here (deg>0 only).
__global__ void agg_kernel(float* __restrict__ out,
                           const float* __restrict__ bias,
                           const float* __restrict__ b_lin, int nsrc) {
    int wid = (blockIdx.x * blockDim.x + threadIdx.x) >> 5;
    int lane = threadIdx.x & 31;
    if (wid >= nsrc) return;
    int start = g_base[wid];
    int deg   = g_deg[wid];

    float4 acc = ((const float4*)bias)[lane];
    if (deg > 0) {
        float4 bl = ((const float4*)b_lin)[lane];
        acc.x += bl.x; acc.y += bl.y; acc.z += bl.z; acc.w += bl.w;
        for (int p = start; p < start + deg; ++p) {
            unsigned long long r = g_srec[p];
            int ti = (int)(unsigned)(r & 0xffffffffu);
            float att = __int_as_float((int)(r >> 32));
            float4 v = ((const float4*)(g_tgt_hl + (size_t)ti * HID))[lane];
            acc.x += att * v.x; acc.y += att * v.y;
            acc.z += att * v.z; acc.w += att * v.w;
        }
    }
    ((float4*)(out + (size_t)wid * HID))[lane] = acc;
}

// ---------------- launch -----------------------------------------------------------
extern "C" void kernel_launch(void* const* d_in, const int* in_sizes, int n_in,
                              void* d_out, int out_size) {
    const float* source_h   = (const float*)d_in[0];
    const float* target_h   = (const float*)d_in[1];
    const void*  edges      = d_in[2];
    const float* W          = (const float*)d_in[3];
    const float* b_lin      = (const float*)d_in[4];
    const float* att_w      = (const float*)d_in[5];
    const float* att_b      = (const float*)d_in[6];
    const float* bias       = (const float*)d_in[7];

    int nsrc = in_sizes[0] / IN_F;
    int ntgt = in_sizes[1] / IN_F;
    int E    = in_sizes[2] / 2;
    float* out = (float*)d_out;
    int nb = (nsrc + 1023) / 1024;

    detect_kernel<<<1, 1>>>((const int*)edges);
    proj_kernel<<<1, 256>>>(W, b_lin, att_w, att_b);
    zero_kernel<<<(nsrc + 255) / 256, 256>>>(nsrc);
    score_kernel<<<(int)(((long long)(nsrc + ntgt) * 32 + 255) / 256), 256>>>(
        source_h, target_h, nsrc, ntgt);
    mma_gemm_kernel<<<(ntgt + 127) / 128, 256>>>(target_h, W, ntgt);
    edge1_kernel<<<(E + 255) / 256, 256>>>(edges, E);
    scan1_kernel<<<nb, 1024>>>(nsrc);
    scan2_kernel<<<1, 128>>>(nb);
    scan3_kernel<<<(nsrc + 255) / 256, 256>>>(nsrc);
    scatter_kernel<<<(E + 255) / 256, 256>>>(edges, E);
    agg_kernel<<<(int)(((long long)nsrc * 32 + 255) / 256), 256>>>(
        out, bias, b_lin, nsrc);
}

// round 8
// speedup vs baseline: 2.7243x; 1.1017x over previous
#include <cuda_runtime.h>
#include <cuda_bf16.h>
#include <mma.h>
#include <math.h>
#include <stdint.h>

using namespace nvcuda;

#define NMAX   100000
#define EMAX   1600000
#define IN_F   256
#define HID    128

// ---------------- device scratch (static; no allocations allowed) -------------
// Padded by 128 rows: boundary GEMM tile stores unguarded into the pad.
__device__ __align__(16) float g_tgt_hl[(size_t)(NMAX + 128) * HID];
__device__ __align__(16) float g_sscore[NMAX];
__device__ __align__(16) float g_tscore[NMAX];
__device__ __align__(16) unsigned long long g_srec[EMAX];   // packed (ex, ti)
__device__ int g_deg[NMAX];
__device__ int g_base[NMAX];
__device__ int g_cursor[NMAX];
__device__ int g_bsum[128];
__device__ __align__(16) float g_wsproj[IN_F];
__device__ __align__(16) float g_wtproj[IN_F];
__device__ __align__(16) __nv_bfloat16 g_Wh[HID * IN_F];
__device__ __align__(16) __nv_bfloat16 g_Wl[HID * IN_F];
__device__ float g_cs;
__device__ float g_ct;
__device__ int   g_idx64;

// ---------------- edge index accessor ------------------------------------------
__device__ __forceinline__ int edge_at(const void* e, int is64, long long pos) {
    if (is64) return (int)((const long long*)e)[pos];
    return ((const int*)e)[pos];
}
__global__ void detect_kernel(const int* __restrict__ edges_i32) {
    int nz = 0;
    for (int i = 1; i < 256; i += 2) nz += (edges_i32[i] != 0);
    g_idx64 = (nz == 0) ? 1 : 0;
}

// ---------------- proj + W hi/lo split ------------------------------------------
__global__ void proj_kernel(const float* __restrict__ W,
                            const float* __restrict__ b_lin,
                            const float* __restrict__ att_w,
                            const float* __restrict__ att_b) {
    int k = threadIdx.x;
    float s = 0.f, t = 0.f;
#pragma unroll 8
    for (int h = 0; h < HID; ++h) {
        float w = W[h * IN_F + k];
        s += w * att_w[h];
        t += w * att_w[HID + h];
    }
    g_wsproj[k] = s;
    g_wtproj[k] = t;
    if (k == 0) {
        float cs = 0.f, ct = 0.f;
        for (int h = 0; h < HID; ++h) {
            cs += b_lin[h] * att_w[h];
            ct += b_lin[h] * att_w[HID + h];
        }
        g_cs = cs;
        g_ct = ct + att_b[0];
    }
}

__global__ void wsplit_kernel(const float* __restrict__ W) {
    int i = blockIdx.x * 256 + threadIdx.x;   // 32768 total
    float w = W[i];
    __nv_bfloat16 h = __float2bfloat16(w);
    g_Wh[i] = h;
    g_Wl[i] = __float2bfloat16(w - __bfloat162float(h));
}

__global__ void zero_kernel(int nsrc) {
    int i = blockIdx.x * blockDim.x + threadIdx.x;
    if (i < nsrc) g_deg[i] = 0;
}

// ---------------- source scores only (warp per node) ----------------------------
__global__ void score_kernel(const float* __restrict__ src, int nsrc) {
    int gtid = blockIdx.x * blockDim.x + threadIdx.x;
    int wid = gtid >> 5;
    int lane = gtid & 31;
    if (wid >= nsrc) return;
    const float* row = src + (size_t)wid * IN_F;

    float4 a = ((const float4*)row)[lane];
    float4 b = ((const float4*)row)[lane + 32];
    float4 pa = ((const float4*)g_wsproj)[lane];
    float4 pb = ((const float4*)g_wsproj)[lane + 32];
    float d = a.x * pa.x + a.y * pa.y + a.z * pa.z + a.w * pa.w
            + b.x * pb.x + b.y * pb.y + b.z * pb.z + b.w * pb.w;
#pragma unroll
    for (int o = 16; o; o >>= 1) d += __shfl_down_sync(0xFFFFFFFFu, d, o);
    if (lane == 0) g_sscore[wid] = d + g_cs;
}

// ================= wmma split-bf16 GEMM + fused t_score ========================
// g_tgt_hl[M,128] = A[M,256] @ W^T  (b_lin folded into agg via sum(att)=1)
// D = Ahi*Whi + Ahi*Wlo + Alo*Whi ; t_score fused into the A streaming loop.
#define LDT 40   // padded bf16 row pitch

__global__ void __launch_bounds__(256)
mma_gemm_kernel(const float* __restrict__ A, int M) {
    __shared__ __nv_bfloat16 sAh[128 * LDT];
    __shared__ __nv_bfloat16 sAl[128 * LDT];
    __shared__ __nv_bfloat16 sWh[128 * LDT];
    __shared__ __nv_bfloat16 sWl[128 * LDT];

    int tid = threadIdx.x;
    int warp = tid >> 5;
    int wm = warp & 1;        // 2 warps in M: 64 rows each
    int wn = warp >> 1;       // 4 warps in N: 32 cols each
    int row0 = blockIdx.x * 128;

    wmma::fragment<wmma::accumulator, 16, 16, 16, float> acc[4][2];
#pragma unroll
    for (int i = 0; i < 4; ++i)
#pragma unroll
        for (int j = 0; j < 2; ++j) wmma::fill_fragment(acc[i][j], 0.f);

    float tsc[4] = {0.f, 0.f, 0.f, 0.f};   // partial t_score per owned row

    for (int k0 = 0; k0 < IN_F; k0 += 32) {
#pragma unroll
        for (int q = 0; q < 4; ++q) {
            int idx = tid + q * 256;         // 0..1023
            int r = idx >> 3;                // 0..127
            int c4 = (idx & 7) * 4;          // 0..28
            // W tiles: precomputed bf16, straight copy
            *(uint2*)&sWh[r * LDT + c4] =
                *(const uint2*)&g_Wh[r * IN_F + k0 + c4];
            *(uint2*)&sWl[r * LDT + c4] =
                *(const uint2*)&g_Wl[r * IN_F + k0 + c4];
            // A tile: load fp32, fused t_score dot, hi/lo split
            float4 v = make_float4(0.f, 0.f, 0.f, 0.f);
            int grow = row0 + r;
            if (grow < M) v = *(const float4*)(A + (size_t)grow * IN_F + k0 + c4);
            tsc[q] += v.x * g_wtproj[k0 + c4]     + v.y * g_wtproj[k0 + c4 + 1]
                    + v.z * g_wtproj[k0 + c4 + 2] + v.w * g_wtproj[k0 + c4 + 3];
            __nv_bfloat162 h01 = __floats2bfloat162_rn(v.x, v.y);
            __nv_bfloat162 h23 = __floats2bfloat162_rn(v.z, v.w);
            __nv_bfloat162 l01 = __floats2bfloat162_rn(
                v.x - __bfloat162float(h01.x), v.y - __bfloat162float(h01.y));
            __nv_bfloat162 l23 = __floats2bfloat162_rn(
                v.z - __bfloat162float(h23.x), v.w - __bfloat162float(h23.y));
            *(uint2*)&sAh[r * LDT + c4] =
                make_uint2(*(uint32_t*)&h01, *(uint32_t*)&h23);
            *(uint2*)&sAl[r * LDT + c4] =
                make_uint2(*(uint32_t*)&l01, *(uint32_t*)&l23);
        }
        __syncthreads();

#pragma unroll
        for (int kf = 0; kf < 2; ++kf) {
            wmma::fragment<wmma::matrix_a, 16, 16, 16, __nv_bfloat16,
                           wmma::row_major> ah[4], al[4];
            wmma::fragment<wmma::matrix_b, 16, 16, 16, __nv_bfloat16,
                           wmma::col_major> bh[2], bl[2];
#pragma unroll
            for (int i = 0; i < 4; ++i) {
                int r = wm * 64 + i * 16;
                wmma::load_matrix_sync(ah[i], sAh + r * LDT + kf * 16, LDT);
                wmma::load_matrix_sync(al[i], sAl + r * LDT + kf * 16, LDT);
            }
#pragma unroll
            for (int j = 0; j < 2; ++j) {
                int n = wn * 32 + j * 16;
                wmma::load_matrix_sync(bh[j], sWh + n * LDT + kf * 16, LDT);
                wmma::load_matrix_sync(bl[j], sWl + n * LDT + kf * 16, LDT);
            }
#pragma unroll
            for (int i = 0; i < 4; ++i)
#pragma unroll
                for (int j = 0; j < 2; ++j) {
                    wmma::mma_sync(acc[i][j], ah[i], bh[j], acc[i][j]);
                    wmma::mma_sync(acc[i][j], ah[i], bl[j], acc[i][j]);
                    wmma::mma_sync(acc[i][j], al[i], bh[j], acc[i][j]);
                }
        }
        __syncthreads();
    }

    // t_score reduction: 8 consecutive lanes share one row
#pragma unroll
    for (int q = 0; q < 4; ++q) {
        float d = tsc[q];
        d += __shfl_down_sync(0xFFFFFFFFu, d, 4, 8);
        d += __shfl_down_sync(0xFFFFFFFFu, d, 2, 8);
        d += __shfl_down_sync(0xFFFFFFFFu, d, 1, 8);
        if ((tid & 7) == 0) {
            int grow = row0 + ((tid + q * 256) >> 3);
            if (grow < M) g_tscore[grow] = d + g_ct;
        }
    }

#pragma unroll
    for (int i = 0; i < 4; ++i)
#pragma unroll
        for (int j = 0; j < 2; ++j) {
            size_t r = (size_t)row0 + wm * 64 + i * 16;   // pad covers overrun
            int n = wn * 32 + j * 16;
            wmma::store_matrix_sync(g_tgt_hl + r * HID + n, acc[i][j], HID,
                                    wmma::mem_row_major);
        }
}

// ---------------- degree histogram (reads si only) -------------------------------
__global__ void hist_kernel(const void* __restrict__ edges, int E) {
    int i = blockIdx.x * blockDim.x + threadIdx.x;
    if (i >= E) return;
    int si = edge_at(edges, g_idx64, i);
    atomicAdd(&g_deg[si], 1);
}

// ---------------- exclusive scan of degrees --------------------------------------
__global__ void scan1_kernel(int n) {
    __shared__ int s[1024];
    int i = blockIdx.x * 1024 + threadIdx.x;
    int v = (i < n) ? g_deg[i] : 0;
    s[threadIdx.x] = v;
    __syncthreads();
#pragma unroll
    for (int o = 1; o < 1024; o <<= 1) {
        int t = (threadIdx.x >= o) ? s[threadIdx.x - o] : 0;
        __syncthreads();
        s[threadIdx.x] += t;
        __syncthreads();
    }
    if (i < n) g_base[i] = s[threadIdx.x] - v;
    if (threadIdx.x == 1023) g_bsum[blockIdx.x] = s[1023];
}
__global__ void scan2_kernel(int nb) {
    __shared__ int s[128];
    int v = (threadIdx.x < nb) ? g_bsum[threadIdx.x] : 0;
    s[threadIdx.x] = v;
    __syncthreads();
#pragma unroll
    for (int o = 1; o < 128; o <<= 1) {
        int t = (threadIdx.x >= o) ? s[threadIdx.x - o] : 0;
        __syncthreads();
        s[threadIdx.x] += t;
        __syncthreads();
    }
    if (threadIdx.x < nb) g_bsum[threadIdx.x] = s[threadIdx.x] - v;
}
__global__ void scan3_kernel(int n) {
    int i = blockIdx.x * blockDim.x + threadIdx.x;
    if (i < n) {
        int b = g_base[i] + g_bsum[i >> 10];
        g_base[i] = b;
        g_cursor[i] = b;
    }
}

// ---------------- scatter: compute ex and write (ex, ti) sorted by si ------------
// e in [-1,1] (tanh): segment-max cancels mathematically in the softmax.
__global__ void scatter_kernel(const void* __restrict__ edges, int E) {
    int i = blockIdx.x * blockDim.x + threadIdx.x;
    if (i >= E) return;
    int is64 = g_idx64;
    int si = edge_at(edges, is64, i);
    int ti = edge_at(edges, is64, (long long)E + i);
    float e = tanhf(g_sscore[si] + g_tscore[ti]);
    float ex = __expf(e);
    int pos = atomicAdd(&g_cursor[si], 1);
    g_srec[pos] = ((unsigned long long)(unsigned)__float_as_int(ex) << 32)
                | (unsigned)ti;
}

// ---------------- aggregate (warp per source node) --------------------------------
// out = (sum ex*v)/(sum ex) + b_lin + bias   (deg>0; else bias only)
__global__ void agg_kernel(float* __restrict__ out,
                           const float* __restrict__ bias,
                           const float* __restrict__ b_lin, int nsrc) {
    int wid = (blockIdx.x * blockDim.x + threadIdx.x) >> 5;
    int lane = threadIdx.x & 31;
    if (wid >= nsrc) return;
    int start = g_base[wid];
    int deg   = g_deg[wid];

    float4 res = ((const float4*)bias)[lane];
    if (deg > 0) {
        float4 acc = make_float4(0.f, 0.f, 0.f, 0.f);
        float denom = 0.f;
        for (int p = start; p < start + deg; ++p) {
            unsigned long long r = g_srec[p];
            int ti = (int)(unsigned)(r & 0xffffffffu);
            float ex = __int_as_float((int)(r >> 32));
            denom += ex;
            float4 v = ((const float4*)(g_tgt_hl + (size_t)ti * HID))[lane];
            acc.x += ex * v.x; acc.y += ex * v.y;
            acc.z += ex * v.z; acc.w += ex * v.w;
        }
        float inv = 1.f / denom;
        float4 bl = ((const float4*)b_lin)[lane];
        res.x += bl.x + acc.x * inv; res.y += bl.y + acc.y * inv;
        res.z += bl.z + acc.z * inv; res.w += bl.w + acc.w * inv;
    }
    ((float4*)(out + (size_t)wid * HID))[lane] = res;
}

// ---------------- launch -----------------------------------------------------------
extern "C" void kernel_launch(void* const* d_in, const int* in_sizes, int n_in,
                              void* d_out, int out_size) {
    const float* source_h   = (const float*)d_in[0];
    const float* target_h   = (const float*)d_in[1];
    const void*  edges      = d_in[2];
    const float* W          = (const float*)d_in[3];
    const float* b_lin      = (const float*)d_in[4];
    const float* att_w      = (const float*)d_in[5];
    const float* att_b      = (const float*)d_in[6];
    const float* bias       = (const float*)d_in[7];

    int nsrc = in_sizes[0] / IN_F;
    int ntgt = in_sizes[1] / IN_F;
    int E    = in_sizes[2] / 2;
    float* out = (float*)d_out;
    int nb = (nsrc + 1023) / 1024;

    detect_kernel<<<1, 1>>>((const int*)edges);
    proj_kernel<<<1, 256>>>(W, b_lin, att_w, att_b);
    wsplit_kernel<<<(HID * IN_F) / 256, 256>>>(W);
    zero_kernel<<<(nsrc + 255) / 256, 256>>>(nsrc);
    hist_kernel<<<(E + 255) / 256, 256>>>(edges, E);
    score_kernel<<<(int)(((long long)nsrc * 32 + 255) / 256), 256>>>(
        source_h, nsrc);
    mma_gemm_kernel<<<(ntgt + 127) / 128, 256>>>(target_h, ntgt);
    scan1_kernel<<<nb, 1024>>>(nsrc);
    scan2_kernel<<<1, 128>>>(nb);
    scan3_kernel<<<(nsrc + 255) / 256, 256>>>(nsrc);
    scatter_kernel<<<(E + 255) / 256, 256>>>(edges, E);
    agg_kernel<<<(int)(((long long)nsrc * 32 + 255) / 256), 256>>>(
        out, bias, b_lin, nsrc);
}

// round 9
// speedup vs baseline: 2.9038x; 1.0659x over previous
#include <cuda_runtime.h>
#include <cuda_bf16.h>
#include <cuda_fp16.h>
#include <mma.h>
#include <math.h>
#include <stdint.h>

using namespace nvcuda;

#define NMAX   100000
#define EMAX   1600000
#define IN_F   256
#define HID    128

// ---------------- device scratch (static; no allocations allowed) -------------
// tgt_hl stored fp16 (halves the agg gather traffic; t_score kept fp32).
// Padded by 128 rows: boundary GEMM tile stores unguarded into the pad.
__device__ __align__(16) __half g_tgt_hl[(size_t)(NMAX + 128) * HID];
__device__ __align__(16) float g_sscore[NMAX];
__device__ __align__(16) float g_tscore[NMAX];
__device__ __align__(16) unsigned long long g_srec[EMAX];   // packed (ex, ti)
__device__ int g_deg[NMAX];
__device__ int g_base[NMAX];
__device__ int g_cursor[NMAX];
__device__ int g_bsum[128];
__device__ __align__(16) float g_wsproj[IN_F];
__device__ __align__(16) float g_wtproj[IN_F];
__device__ __align__(16) __nv_bfloat16 g_Wh[HID * IN_F];
__device__ __align__(16) __nv_bfloat16 g_Wl[HID * IN_F];
__device__ float g_cs;
__device__ float g_ct;
__device__ int   g_idx64;

// ---------------- edge index accessor ------------------------------------------
__device__ __forceinline__ int edge_at(const void* e, int is64, long long pos) {
    if (is64) return (int)((const long long*)e)[pos];
    return ((const int*)e)[pos];
}

// ---------------- fused setup: detect + proj + W split + zero deg ---------------
__global__ void setup_kernel(const float* __restrict__ W,
                             const float* __restrict__ b_lin,
                             const float* __restrict__ att_w,
                             const float* __restrict__ att_b,
                             const int* __restrict__ edges_i32, int nsrc) {
    int b = blockIdx.x, tid = threadIdx.x;
    if (b == 0) {
        // proj: ws/wt = W^T @ att halves
        float s = 0.f, t = 0.f;
#pragma unroll 8
        for (int h = 0; h < HID; ++h) {
            float w = W[h * IN_F + tid];
            s += w * att_w[h];
            t += w * att_w[HID + h];
        }
        g_wsproj[tid] = s;
        g_wtproj[tid] = t;
        if (tid == 0) {
            float cs = 0.f, ct = 0.f;
            for (int h = 0; h < HID; ++h) {
                cs += b_lin[h] * att_w[h];
                ct += b_lin[h] * att_w[HID + h];
            }
            g_cs = cs;
            g_ct = ct + att_b[0];
        }
        // detect int64 vs int32 edges: int64 => all odd words are zero high-words
        __shared__ int sflag;
        if (tid == 0) sflag = 0;
        __syncthreads();
        if (tid < 128 && edges_i32[2 * tid + 1] != 0) sflag = 1;
        __syncthreads();
        if (tid == 0) g_idx64 = (sflag == 0) ? 1 : 0;
    } else if (b <= 128) {
        int i = (b - 1) * 256 + tid;       // 32768 W elements
        float w = W[i];
        __nv_bfloat16 h = __float2bfloat16(w);
        g_Wh[i] = h;
        g_Wl[i] = __float2bfloat16(w - __bfloat162float(h));
    } else {
        int i = (b - 129) * 256 + tid;
        if (i < nsrc) g_deg[i] = 0;
    }
}

// ---------------- source scores (warp per node) ----------------------------------
__global__ void score_kernel(const float* __restrict__ src, int nsrc) {
    int gtid = blockIdx.x * blockDim.x + threadIdx.x;
    int wid = gtid >> 5;
    int lane = gtid & 31;
    if (wid >= nsrc) return;
    const float* row = src + (size_t)wid * IN_F;

    float4 a = ((const float4*)row)[lane];
    float4 b = ((const float4*)row)[lane + 32];
    float4 pa = ((const float4*)g_wsproj)[lane];
    float4 pb = ((const float4*)g_wsproj)[lane + 32];
    float d = a.x * pa.x + a.y * pa.y + a.z * pa.z + a.w * pa.w
            + b.x * pb.x + b.y * pb.y + b.z * pb.z + b.w * pb.w;
#pragma unroll
    for (int o = 16; o; o >>= 1) d += __shfl_down_sync(0xFFFFFFFFu, d, o);
    if (lane == 0) g_sscore[wid] = d + g_cs;
}

// ================= wmma split-bf16 GEMM + fused t_score ========================
// g_tgt_hl[M,128] = fp16( A[M,256] @ W^T )  (b_lin folded into agg, sum(att)=1)
// D = Ahi*Whi + Ahi*Wlo + Alo*Whi. Register prefetch overlaps LDG with MMA.
#define LDT 40   // padded bf16 row pitch

__global__ void __launch_bounds__(256)
mma_gemm_kernel(const float* __restrict__ A, int M) {
    __shared__ __align__(16) __nv_bfloat16 smem_all[4 * 128 * LDT];
    __nv_bfloat16* sAh = smem_all;
    __nv_bfloat16* sAl = smem_all + 128 * LDT;
    __nv_bfloat16* sWh = smem_all + 2 * 128 * LDT;
    __nv_bfloat16* sWl = smem_all + 3 * 128 * LDT;

    int tid = threadIdx.x;
    int warp = tid >> 5;
    int lane = tid & 31;
    int wm = warp & 1;        // 2 warps in M: 64 rows each
    int wn = warp >> 1;       // 4 warps in N: 32 cols each
    int row0 = blockIdx.x * 128;

    // per-q fixed coordinates
    int rq[4], cq[4], gq[4];
#pragma unroll
    for (int q = 0; q < 4; ++q) {
        int idx = tid + q * 256;
        rq[q] = idx >> 3;
        cq[q] = (idx & 7) * 4;
        gq[q] = row0 + rq[q];
    }

    wmma::fragment<wmma::accumulator, 16, 16, 16, float> acc[4][2];
#pragma unroll
    for (int i = 0; i < 4; ++i)
#pragma unroll
        for (int j = 0; j < 2; ++j) wmma::fill_fragment(acc[i][j], 0.f);

    float tsc[4] = {0.f, 0.f, 0.f, 0.f};
    float4 pva[4];
    uint2 pwh[4], pwl[4];

    // prefetch tile k0=0
#pragma unroll
    for (int q = 0; q < 4; ++q) {
        pva[q] = make_float4(0.f, 0.f, 0.f, 0.f);
        if (gq[q] < M) pva[q] = *(const float4*)(A + (size_t)gq[q] * IN_F + cq[q]);
        pwh[q] = *(const uint2*)&g_Wh[rq[q] * IN_F + cq[q]];
        pwl[q] = *(const uint2*)&g_Wl[rq[q] * IN_F + cq[q]];
    }

    for (int k0 = 0; k0 < IN_F; k0 += 32) {
        // convert & store current tile from registers
#pragma unroll
        for (int q = 0; q < 4; ++q) {
            int r = rq[q], c4 = cq[q];
            *(uint2*)&sWh[r * LDT + c4] = pwh[q];
            *(uint2*)&sWl[r * LDT + c4] = pwl[q];
            float4 v = pva[q];
            tsc[q] += v.x * g_wtproj[k0 + c4]     + v.y * g_wtproj[k0 + c4 + 1]
                    + v.z * g_wtproj[k0 + c4 + 2] + v.w * g_wtproj[k0 + c4 + 3];
            __nv_bfloat162 h01 = __floats2bfloat162_rn(v.x, v.y);
            __nv_bfloat162 h23 = __floats2bfloat162_rn(v.z, v.w);
            __nv_bfloat162 l01 = __floats2bfloat162_rn(
                v.x - __bfloat162float(h01.x), v.y - __bfloat162float(h01.y));
            __nv_bfloat162 l23 = __floats2bfloat162_rn(
                v.z - __bfloat162float(h23.x), v.w - __bfloat162float(h23.y));
            *(uint2*)&sAh[r * LDT + c4] =
                make_uint2(*(uint32_t*)&h01, *(uint32_t*)&h23);
            *(uint2*)&sAl[r * LDT + c4] =
                make_uint2(*(uint32_t*)&l01, *(uint32_t*)&l23);
        }
        __syncthreads();

        // prefetch next tile (LDGs in flight during MMA section)
        int kn = k0 + 32;
        if (kn < IN_F) {
#pragma unroll
            for (int q = 0; q < 4; ++q) {
                pva[q] = make_float4(0.f, 0.f, 0.f, 0.f);
                if (gq[q] < M)
                    pva[q] = *(const float4*)(A + (size_t)gq[q] * IN_F + kn + cq[q]);
                pwh[q] = *(const uint2*)&g_Wh[rq[q] * IN_F + kn + cq[q]];
                pwl[q] = *(const uint2*)&g_Wl[rq[q] * IN_F + kn + cq[q]];
            }
        }

#pragma unroll
        for (int kf = 0; kf < 2; ++kf) {
            wmma::fragment<wmma::matrix_a, 16, 16, 16, __nv_bfloat16,
                           wmma::row_major> ah[4], al[4];
            wmma::fragment<wmma::matrix_b, 16, 16, 16, __nv_bfloat16,
                           wmma::col_major> bh[2], bl[2];
#pragma unroll
            for (int i = 0; i < 4; ++i) {
                int r = wm * 64 + i * 16;
                wmma::load_matrix_sync(ah[i], sAh + r * LDT + kf * 16, LDT);
                wmma::load_matrix_sync(al[i], sAl + r * LDT + kf * 16, LDT);
            }
#pragma unroll
            for (int j = 0; j < 2; ++j) {
                int n = wn * 32 + j * 16;
                wmma::load_matrix_sync(bh[j], sWh + n * LDT + kf * 16, LDT);
                wmma::load_matrix_sync(bl[j], sWl + n * LDT + kf * 16, LDT);
            }
#pragma unroll
            for (int i = 0; i < 4; ++i)
#pragma unroll
                for (int j = 0; j < 2; ++j) {
                    wmma::mma_sync(acc[i][j], ah[i], bh[j], acc[i][j]);
                    wmma::mma_sync(acc[i][j], ah[i], bl[j], acc[i][j]);
                    wmma::mma_sync(acc[i][j], al[i], bh[j], acc[i][j]);
                }
        }
        __syncthreads();
    }

    // t_score reduction: 8 consecutive lanes share one row
#pragma unroll
    for (int q = 0; q < 4; ++q) {
        float d = tsc[q];
        d += __shfl_down_sync(0xFFFFFFFFu, d, 4, 8);
        d += __shfl_down_sync(0xFFFFFFFFu, d, 2, 8);
        d += __shfl_down_sync(0xFFFFFFFFu, d, 1, 8);
        if ((tid & 7) == 0 && gq[q] < M) g_tscore[gq[q]] = d + g_ct;
    }

    // epilogue: acc -> per-warp smem stage -> fp16 global (pad covers overrun)
    float* wscr = (float*)smem_all + warp * (16 * 36);
#pragma unroll
    for (int i = 0; i < 4; ++i) {
        wmma::store_matrix_sync(wscr, acc[i][0], 36, wmma::mem_row_major);
        wmma::store_matrix_sync(wscr + 16, acc[i][1], 36, wmma::mem_row_major);
        __syncwarp();
        int row = lane & 15, seg = lane >> 4;
        const float* sp = wscr + row * 36 + seg * 16;
        __half2 h[8];
#pragma unroll
        for (int q = 0; q < 8; ++q) h[q] = __floats2half2_rn(sp[2 * q], sp[2 * q + 1]);
        size_t grow = (size_t)row0 + wm * 64 + i * 16 + row;
        __half* gp = g_tgt_hl + grow * HID + wn * 32 + seg * 16;
        *(uint4*)gp = *(uint4*)&h[0];
        *(uint4*)(gp + 8) = *(uint4*)&h[4];
        __syncwarp();
    }
}

// ---------------- degree histogram (reads si only) -------------------------------
__global__ void hist_kernel(const void* __restrict__ edges, int E) {
    int i = blockIdx.x * blockDim.x + threadIdx.x;
    if (i >= E) return;
    int si = edge_at(edges, g_idx64, i);
    atomicAdd(&g_deg[si], 1);
}

// ---------------- exclusive scan of degrees --------------------------------------
__global__ void scan1_kernel(int n) {
    __shared__ int s[1024];
    int i = blockIdx.x * 1024 + threadIdx.x;
    int v = (i < n) ? g_deg[i] : 0;
    s[threadIdx.x] = v;
    __syncthreads();
#pragma unroll
    for (int o = 1; o < 1024; o <<= 1) {
        int t = (threadIdx.x >= o) ? s[threadIdx.x - o] : 0;
        __syncthreads();
        s[threadIdx.x] += t;
        __syncthreads();
    }
    if (i < n) g_base[i] = s[threadIdx.x] - v;
    if (threadIdx.x == 1023) g_bsum[blockIdx.x] = s[1023];
}
__global__ void scan2_kernel(int nb) {
    __shared__ int s[128];
    int v = (threadIdx.x < nb) ? g_bsum[threadIdx.x] : 0;
    s[threadIdx.x] = v;
    __syncthreads();
#pragma unroll
    for (int o = 1; o < 128; o <<= 1) {
        int t = (threadIdx.x >= o) ? s[threadIdx.x - o] : 0;
        __syncthreads();
        s[threadIdx.x] += t;
        __syncthreads();
    }
    if (threadIdx.x < nb) g_bsum[threadIdx.x] = s[threadIdx.x] - v;
}
__global__ void scan3_kernel(int n) {
    int i = blockIdx.x * blockDim.x + threadIdx.x;
    if (i < n) {
        int b = g_base[i] + g_bsum[i >> 10];
        g_base[i] = b;
        g_cursor[i] = b;
    }
}

// ---------------- scatter: compute ex and write (ex, ti) sorted by si ------------
// e in [-1,1] (tanh): segment-max cancels mathematically in the softmax.
__global__ void scatter_kernel(const void* __restrict__ edges, int E) {
    int i = blockIdx.x * blockDim.x + threadIdx.x;
    if (i >= E) return;
    int is64 = g_idx64;
    int si = edge_at(edges, is64, i);
    int ti = edge_at(edges, is64, (long long)E + i);
    float e = tanhf(g_sscore[si] + g_tscore[ti]);
    float ex = __expf(e);
    int pos = atomicAdd(&g_cursor[si], 1);
    g_srec[pos] = ((unsigned long long)(unsigned)__float_as_int(ex) << 32)
                | (unsigned)ti;
}

// ---------------- aggregate (warp per source node, fp16 rows) ---------------------
// out = (sum ex*v)/(sum ex) + b_lin + bias   (deg>0; else bias only)
__global__ void agg_kernel(float* __restrict__ out,
                           const float* __restrict__ bias,
                           const float* __restrict__ b_lin, int nsrc) {
    int wid = (blockIdx.x * blockDim.x + threadIdx.x) >> 5;
    int lane = threadIdx.x & 31;
    if (wid >= nsrc) return;
    int start = g_base[wid];
    int deg   = g_deg[wid];

    float4 res = ((const float4*)bias)[lane];
    if (deg > 0) {
        float4 acc = make_float4(0.f, 0.f, 0.f, 0.f);
        float denom = 0.f;
        for (int p = start; p < start + deg; ++p) {
            unsigned long long r = g_srec[p];
            int ti = (int)(unsigned)(r & 0xffffffffu);
            float ex = __int_as_float((int)(r >> 32));
            denom += ex;
            uint2 pk = ((const uint2*)(g_tgt_hl + (size_t)ti * HID))[lane];
            float2 f0 = __half22float2(*(__half2*)&pk.x);
            float2 f1 = __half22float2(*(__half2*)&pk.y);
            acc.x += ex * f0.x; acc.y += ex * f0.y;
            acc.z += ex * f1.x; acc.w += ex * f1.y;
        }
        float inv = 1.f / denom;
        float4 bl = ((const float4*)b_lin)[lane];
        res.x += bl.x + acc.x * inv; res.y += bl.y + acc.y * inv;
        res.z += bl.z + acc.z * inv; res.w += bl.w + acc.w * inv;
    }
    ((float4*)(out + (size_t)wid * HID))[lane] = res;
}

// ---------------- launch -----------------------------------------------------------
extern "C" void kernel_launch(void* const* d_in, const int* in_sizes, int n_in,
                              void* d_out, int out_size) {
    const float* source_h   = (const float*)d_in[0];
    const float* target_h   = (const float*)d_in[1];
    const void*  edges      = d_in[2];
    const float* W          = (const float*)d_in[3];
    const float* b_lin      = (const float*)d_in[4];
    const float* att_w      = (const float*)d_in[5];
    const float* att_b      = (const float*)d_in[6];
    const float* bias       = (const float*)d_in[7];

    int nsrc = in_sizes[0] / IN_F;
    int ntgt = in_sizes[1] / IN_F;
    int E    = in_sizes[2] / 2;
    float* out = (float*)d_out;
    int nb = (nsrc + 1023) / 1024;

    setup_kernel<<<129 + (nsrc + 255) / 256, 256>>>(
        W, b_lin, att_w, att_b, (const int*)edges, nsrc);
    hist_kernel<<<(E + 255) / 256, 256>>>(edges, E);
    score_kernel<<<(int)(((long long)nsrc * 32 + 255) / 256), 256>>>(
        source_h, nsrc);
    mma_gemm_kernel<<<(ntgt + 127) / 128, 256>>>(target_h, ntgt);
    scan1_kernel<<<nb, 1024>>>(nsrc);
    scan2_kernel<<<1, 128>>>(nb);
    scan3_kernel<<<(nsrc + 255) / 256, 256>>>(nsrc);
    scatter_kernel<<<(E + 255) / 256, 256>>>(edges, E);
    agg_kernel<<<(int)(((long long)nsrc * 32 + 255) / 256), 256>>>(
        out, bias, b_lin, nsrc);
}

// round 10
// speedup vs baseline: 3.5532x; 1.2236x over previous
#include <cuda_runtime.h>
#include <cuda_fp16.h>
#include <mma.h>
#include <math.h>
#include <stdint.h>

using namespace nvcuda;

#define NMAX   100000
#define EMAX   1600000
#define IN_F   256
#define HID    128

// ---------------- device scratch (static; no allocations allowed) -------------
// tgt_hl stored fp16 (halves agg gather traffic). Padded by 128 rows: boundary
// GEMM tile stores unguarded into the pad.
__device__ __align__(16) __half g_tgt_hl[(size_t)(NMAX + 128) * HID];
__device__ __align__(16) float g_sscore[NMAX];
__device__ __align__(16) float g_tscore[NMAX];
__device__ __align__(16) unsigned long long g_srec[EMAX];   // packed (ex, ti)
__device__ int g_deg[NMAX];
__device__ int g_base[NMAX];
__device__ int g_cursor[NMAX];
__device__ int g_bsum[128];
__device__ __align__(16) float g_wsproj[IN_F];
__device__ __align__(16) float g_wtproj[IN_F];
__device__ __align__(16) __half g_Wh[HID * IN_F];   // fp16 hi of W
__device__ __align__(16) __half g_Wl[HID * IN_F];   // fp16 lo of W (W = hi + lo)
__device__ float g_cs;
__device__ float g_ct;
__device__ int   g_idx64;

// ---------------- edge index accessor ------------------------------------------
__device__ __forceinline__ int edge_at(const void* e, int is64, long long pos) {
    if (is64) return (int)((const long long*)e)[pos];
    return ((const int*)e)[pos];
}

// ---------------- fused setup: detect + proj + W split + zero deg ---------------
__global__ void setup_kernel(const float* __restrict__ W,
                             const float* __restrict__ b_lin,
                             const float* __restrict__ att_w,
                             const float* __restrict__ att_b,
                             const int* __restrict__ edges_i32, int nsrc) {
    int b = blockIdx.x, tid = threadIdx.x;
    if (b == 0) {
        float s = 0.f, t = 0.f;
#pragma unroll 8
        for (int h = 0; h < HID; ++h) {
            float w = W[h * IN_F + tid];
            s += w * att_w[h];
            t += w * att_w[HID + h];
        }
        g_wsproj[tid] = s;
        g_wtproj[tid] = t;
        if (tid == 0) {
            float cs = 0.f, ct = 0.f;
            for (int h = 0; h < HID; ++h) {
                cs += b_lin[h] * att_w[h];
                ct += b_lin[h] * att_w[HID + h];
            }
            g_cs = cs;
            g_ct = ct + att_b[0];
        }
        __shared__ int sflag;
        if (tid == 0) sflag = 0;
        __syncthreads();
        if (tid < 128 && edges_i32[2 * tid + 1] != 0) sflag = 1;
        __syncthreads();
        if (tid == 0) g_idx64 = (sflag == 0) ? 1 : 0;
    } else if (b <= 128) {
        int i = (b - 1) * 256 + tid;       // 32768 W elements
        float w = W[i];
        __half h = __float2half_rn(w);
        g_Wh[i] = h;
        g_Wl[i] = __float2half_rn(w - __half2float(h));
    } else {
        int i = (b - 129) * 256 + tid;
        if (i < nsrc) g_deg[i] = 0;
    }
}

// ---------------- source scores (warp per node) ----------------------------------
__global__ void score_kernel(const float* __restrict__ src, int nsrc) {
    int gtid = blockIdx.x * blockDim.x + threadIdx.x;
    int wid = gtid >> 5;
    int lane = gtid & 31;
    if (wid >= nsrc) return;
    const float* row = src + (size_t)wid * IN_F;

    float4 a = ((const float4*)row)[lane];
    float4 b = ((const float4*)row)[lane + 32];
    float4 pa = ((const float4*)g_wsproj)[lane];
    float4 pb = ((const float4*)g_wsproj)[lane + 32];
    float d = a.x * pa.x + a.y * pa.y + a.z * pa.z + a.w * pa.w
            + b.x * pb.x + b.y * pb.y + b.z * pb.z + b.w * pb.w;
#pragma unroll
    for (int o = 16; o; o >>= 1) d += __shfl_down_sync(0xFFFFFFFFu, d, o);
    if (lane == 0) g_sscore[wid] = d + g_cs;
}

// ================= wmma fp16 W-split GEMM + fused t_score ======================
// g_tgt_hl[M,128] = fp16( A @ W^T ):  D = A16*Whi + A16*Wlo  (W = Whi+Wlo exact;
// only error is A's fp16 quantization ~2.8e-4). 512 threads, warp tile 32x32.
#define LDT 40   // padded fp16 row pitch (80 B)

__global__ void __launch_bounds__(512)
mma_gemm_kernel(const float* __restrict__ A, int M) {
    __shared__ __align__(16) char smem_raw[36864];
    __half* sA  = (__half*)smem_raw;                  // 128*40*2 = 10240 B
    __half* sWh = (__half*)(smem_raw + 10240);
    __half* sWl = (__half*)(smem_raw + 20480);

    int tid = threadIdx.x;
    int warp = tid >> 5;
    int lane = tid & 31;
    int wm = warp & 3;        // 4 warp-rows of 32
    int wn = warp >> 2;       // 4 warp-cols of 32
    int row0 = blockIdx.x * 128;

    // A-load coordinates: 2 float4 per thread per tile
    int rq[2], cq[2], gq[2];
#pragma unroll
    for (int q = 0; q < 2; ++q) {
        int idx = tid + q * 512;          // 0..1023
        rq[q] = idx >> 3;                 // 0..127
        cq[q] = (idx & 7) * 4;            // 0..28
        gq[q] = row0 + rq[q];
    }
    // W-copy coordinates: 1 uint4 (8 halves) per array per thread
    int wr = tid >> 2;                    // 0..127
    int wc = (tid & 3) * 8;               // 0,8,16,24

    wmma::fragment<wmma::accumulator, 16, 16, 16, float> acc[2][2];
#pragma unroll
    for (int i = 0; i < 2; ++i)
#pragma unroll
        for (int j = 0; j < 2; ++j) wmma::fill_fragment(acc[i][j], 0.f);

    float tsc[2] = {0.f, 0.f};
    float4 pva[2];
    uint4 pwh, pwl;

    // prefetch tile k0=0
#pragma unroll
    for (int q = 0; q < 2; ++q) {
        pva[q] = make_float4(0.f, 0.f, 0.f, 0.f);
        if (gq[q] < M) pva[q] = *(const float4*)(A + (size_t)gq[q] * IN_F + cq[q]);
    }
    pwh = *(const uint4*)&g_Wh[wr * IN_F + wc];
    pwl = *(const uint4*)&g_Wl[wr * IN_F + wc];

    for (int k0 = 0; k0 < IN_F; k0 += 32) {
        // store current tile
        *(uint4*)&sWh[wr * LDT + wc] = pwh;
        *(uint4*)&sWl[wr * LDT + wc] = pwl;
#pragma unroll
        for (int q = 0; q < 2; ++q) {
            float4 v = pva[q];
            int c4 = cq[q];
            tsc[q] += v.x * g_wtproj[k0 + c4]     + v.y * g_wtproj[k0 + c4 + 1]
                    + v.z * g_wtproj[k0 + c4 + 2] + v.w * g_wtproj[k0 + c4 + 3];
            __half2 h01 = __floats2half2_rn(v.x, v.y);
            __half2 h23 = __floats2half2_rn(v.z, v.w);
            *(uint2*)&sA[rq[q] * LDT + c4] =
                make_uint2(*(uint32_t*)&h01, *(uint32_t*)&h23);
        }
        __syncthreads();

        // prefetch next tile while MMAs run
        int kn = k0 + 32;
        if (kn < IN_F) {
#pragma unroll
            for (int q = 0; q < 2; ++q) {
                pva[q] = make_float4(0.f, 0.f, 0.f, 0.f);
                if (gq[q] < M)
                    pva[q] = *(const float4*)(A + (size_t)gq[q] * IN_F + kn + cq[q]);
            }
            pwh = *(const uint4*)&g_Wh[wr * IN_F + kn + wc];
            pwl = *(const uint4*)&g_Wl[wr * IN_F + kn + wc];
        }

#pragma unroll
        for (int kf = 0; kf < 2; ++kf) {
            wmma::fragment<wmma::matrix_a, 16, 16, 16, __half,
                           wmma::row_major> af[2];
            wmma::fragment<wmma::matrix_b, 16, 16, 16, __half,
                           wmma::col_major> bh[2], bl[2];
#pragma unroll
            for (int i = 0; i < 2; ++i)
                wmma::load_matrix_sync(af[i],
                    sA + (wm * 32 + i * 16) * LDT + kf * 16, LDT);
#pragma unroll
            for (int j = 0; j < 2; ++j) {
                int n = wn * 32 + j * 16;
                wmma::load_matrix_sync(bh[j], sWh + n * LDT + kf * 16, LDT);
                wmma::load_matrix_sync(bl[j], sWl + n * LDT + kf * 16, LDT);
            }
#pragma unroll
            for (int i = 0; i < 2; ++i)
#pragma unroll
                for (int j = 0; j < 2; ++j) {
                    wmma::mma_sync(acc[i][j], af[i], bh[j], acc[i][j]);
                    wmma::mma_sync(acc[i][j], af[i], bl[j], acc[i][j]);
                }
        }
        __syncthreads();
    }

    // t_score reduction: 8 consecutive lanes share one row
#pragma unroll
    for (int q = 0; q < 2; ++q) {
        float d = tsc[q];
        d += __shfl_down_sync(0xFFFFFFFFu, d, 4, 8);
        d += __shfl_down_sync(0xFFFFFFFFu, d, 2, 8);
        d += __shfl_down_sync(0xFFFFFFFFu, d, 1, 8);
        if ((tid & 7) == 0 && gq[q] < M) g_tscore[gq[q]] = d + g_ct;
    }

    // epilogue: acc -> per-warp smem stage -> fp16 global (pad covers overrun)
    float* wscr = (float*)(smem_raw) + warp * (16 * 36);
#pragma unroll
    for (int i = 0; i < 2; ++i) {
        wmma::store_matrix_sync(wscr, acc[i][0], 36, wmma::mem_row_major);
        wmma::store_matrix_sync(wscr + 16, acc[i][1], 36, wmma::mem_row_major);
        __syncwarp();
        int row = lane & 15, seg = lane >> 4;
        const float* sp = wscr + row * 36 + seg * 16;
        __half2 h[8];
#pragma unroll
        for (int q = 0; q < 8; ++q)
            h[q] = __floats2half2_rn(sp[2 * q], sp[2 * q + 1]);
        size_t grow = (size_t)row0 + wm * 32 + i * 16 + row;
        __half* gp = g_tgt_hl + grow * HID + wn * 32 + seg * 16;
        *(uint4*)gp = *(uint4*)&h[0];
        *(uint4*)(gp + 8) = *(uint4*)&h[4];
        __syncwarp();
    }
}

// ---------------- degree histogram (reads si only) -------------------------------
__global__ void hist_kernel(const void* __restrict__ edges, int E) {
    int i = blockIdx.x * blockDim.x + threadIdx.x;
    if (i >= E) return;
    int si = edge_at(edges, g_idx64, i);
    atomicAdd(&g_deg[si], 1);
}

// ---------------- exclusive scan of degrees --------------------------------------
__global__ void scan1_kernel(int n) {
    __shared__ int s[1024];
    int i = blockIdx.x * 1024 + threadIdx.x;
    int v = (i < n) ? g_deg[i] : 0;
    s[threadIdx.x] = v;
    __syncthreads();
#pragma unroll
    for (int o = 1; o < 1024; o <<= 1) {
        int t = (threadIdx.x >= o) ? s[threadIdx.x - o] : 0;
        __syncthreads();
        s[threadIdx.x] += t;
        __syncthreads();
    }
    if (i < n) g_base[i] = s[threadIdx.x] - v;
    if (threadIdx.x == 1023) g_bsum[blockIdx.x] = s[1023];
}
__global__ void scan2_kernel(int nb) {
    __shared__ int s[128];
    int v = (threadIdx.x < nb) ? g_bsum[threadIdx.x] : 0;
    s[threadIdx.x] = v;
    __syncthreads();
#pragma unroll
    for (int o = 1; o < 128; o <<= 1) {
        int t = (threadIdx.x >= o) ? s[threadIdx.x - o] : 0;
        __syncthreads();
        s[threadIdx.x] += t;
        __syncthreads();
    }
    if (threadIdx.x < nb) g_bsum[threadIdx.x] = s[threadIdx.x] - v;
}
__global__ void scan3_kernel(int n) {
    int i = blockIdx.x * blockDim.x + threadIdx.x;
    if (i < n) {
        int b = g_base[i] + g_bsum[i >> 10];
        g_base[i] = b;
        g_cursor[i] = b;
    }
}

// ---------------- scatter: compute ex and write (ex, ti) sorted by si ------------
// e in [-1,1] (tanh): segment-max cancels mathematically in the softmax.
__global__ void scatter_kernel(const void* __restrict__ edges, int E) {
    int i = blockIdx.x * blockDim.x + threadIdx.x;
    if (i >= E) return;
    int is64 = g_idx64;
    int si = edge_at(edges, is64, i);
    int ti = edge_at(edges, is64, (long long)E + i);
    float e = tanhf(g_sscore[si] + g_tscore[ti]);
    float ex = __expf(e);
    int pos = atomicAdd(&g_cursor[si], 1);
    g_srec[pos] = ((unsigned long long)(unsigned)__float_as_int(ex) << 32)
                | (unsigned)ti;
}

// ---------------- aggregate (warp per source node, fp16 rows) ---------------------
// out = (sum ex*v)/(sum ex) + b_lin + bias   (deg>0; else bias only)
__global__ void agg_kernel(float* __restrict__ out,
                           const float* __restrict__ bias,
                           const float* __restrict__ b_lin, int nsrc) {
    int wid = (blockIdx.x * blockDim.x + threadIdx.x) >> 5;
    int lane = threadIdx.x & 31;
    if (wid >= nsrc) return;
    int start = g_base[wid];
    int deg   = g_deg[wid];

    float4 res = ((const float4*)bias)[lane];
    if (deg > 0) {
        float4 acc = make_float4(0.f, 0.f, 0.f, 0.f);
        float denom = 0.f;
        for (int p = start; p < start + deg; ++p) {
            unsigned long long r = g_srec[p];
            int ti = (int)(unsigned)(r & 0xffffffffu);
            float ex = __int_as_float((int)(r >> 32));
            denom += ex;
            uint2 pk = ((const uint2*)(g_tgt_hl + (size_t)ti * HID))[lane];
            float2 f0 = __half22float2(*(__half2*)&pk.x);
            float2 f1 = __half22float2(*(__half2*)&pk.y);
            acc.x += ex * f0.x; acc.y += ex * f0.y;
            acc.z += ex * f1.x; acc.w += ex * f1.y;
        }
        float inv = 1.f / denom;
        float4 bl = ((const float4*)b_lin)[lane];
        res.x += bl.x + acc.x * inv; res.y += bl.y + acc.y * inv;
        res.z += bl.z + acc.z * inv; res.w += bl.w + acc.w * inv;
    }
    ((float4*)(out + (size_t)wid * HID))[lane] = res;
}

// ---------------- launch -----------------------------------------------------------
extern "C" void kernel_launch(void* const* d_in, const int* in_sizes, int n_in,
                              void* d_out, int out_size) {
    const float* source_h   = (const float*)d_in[0];
    const float* target_h   = (const float*)d_in[1];
    const void*  edges      = d_in[2];
    const float* W          = (const float*)d_in[3];
    const float* b_lin      = (const float*)d_in[4];
    const float* att_w      = (const float*)d_in[5];
    const float* att_b      = (const float*)d_in[6];
    const float* bias       = (const float*)d_in[7];

    int nsrc = in_sizes[0] / IN_F;
    int ntgt = in_sizes[1] / IN_F;
    int E    = in_sizes[2] / 2;
    float* out = (float*)d_out;
    int nb = (nsrc + 1023) / 1024;

    setup_kernel<<<129 + (nsrc + 255) / 256, 256>>>(
        W, b_lin, att_w, att_b, (const int*)edges, nsrc);
    hist_kernel<<<(E + 255) / 256, 256>>>(edges, E);
    score_kernel<<<(int)(((long long)nsrc * 32 + 255) / 256), 256>>>(
        source_h, nsrc);
    mma_gemm_kernel<<<(ntgt + 127) / 128, 512>>>(target_h, ntgt);
    scan1_kernel<<<nb, 1024>>>(nsrc);
    scan2_kernel<<<1, 128>>>(nb);
    scan3_kernel<<<(nsrc + 255) / 256, 256>>>(nsrc);
    scatter_kernel<<<(E + 255) / 256, 256>>>(edges, E);
    agg_kernel<<<(int)(((long long)nsrc * 32 + 255) / 256), 256>>>(
        out, bias, b_lin, nsrc);
}

// round 11
// speedup vs baseline: 3.9000x; 1.0976x over previous
#include <cuda_runtime.h>
#include <cuda_fp16.h>
#include <mma.h>
#include <math.h>
#include <stdint.h>

using namespace nvcuda;

#define NMAX   100000
#define EMAX   1600000
#define IN_F   256
#define HID    128

// ---------------- device scratch (static; no allocations allowed) -------------
// tgt_hl stored fp16 (halves agg gather traffic). Padded by 128 rows: boundary
// GEMM tile stores unguarded into the pad.
__device__ __align__(16) __half g_tgt_hl[(size_t)(NMAX + 128) * HID];
__device__ __align__(16) float g_sscore[NMAX];
__device__ __align__(16) float g_tscore[NMAX];
__device__ __align__(16) unsigned long long g_srec[EMAX];   // packed (ex, ti)
__device__ int g_deg[NMAX];
__device__ int g_base[NMAX];
__device__ int g_cursor[NMAX];
__device__ int g_bsum[128];
__device__ __align__(16) float g_wsproj[IN_F];
__device__ __align__(16) float g_wtproj[IN_F];
__device__ __align__(16) __half g_Wh[HID * IN_F];   // fp16 W (rounded)
__device__ float g_cs;
__device__ float g_ct;
__device__ int   g_idx64;

// ---------------- edge index accessor ------------------------------------------
__device__ __forceinline__ int edge_at(const void* e, int is64, long long pos) {
    if (is64) return (int)((const long long*)e)[pos];
    return ((const int*)e)[pos];
}

// ---------------- fused setup: detect + proj + W fp16 + zero deg ----------------
__global__ void setup_kernel(const float* __restrict__ W,
                             const float* __restrict__ b_lin,
                             const float* __restrict__ att_w,
                             const float* __restrict__ att_b,
                             const int* __restrict__ edges_i32, int nsrc) {
    int b = blockIdx.x, tid = threadIdx.x;
    if (b == 0) {
        float s = 0.f, t = 0.f;
#pragma unroll 8
        for (int h = 0; h < HID; ++h) {
            float w = W[h * IN_F + tid];
            s += w * att_w[h];
            t += w * att_w[HID + h];
        }
        g_wsproj[tid] = s;
        g_wtproj[tid] = t;
        if (tid == 0) {
            float cs = 0.f, ct = 0.f;
            for (int h = 0; h < HID; ++h) {
                cs += b_lin[h] * att_w[h];
                ct += b_lin[h] * att_w[HID + h];
            }
            g_cs = cs;
            g_ct = ct + att_b[0];
        }
        __shared__ int sflag;
        if (tid == 0) sflag = 0;
        __syncthreads();
        if (tid < 128 && edges_i32[2 * tid + 1] != 0) sflag = 1;
        __syncthreads();
        if (tid == 0) g_idx64 = (sflag == 0) ? 1 : 0;
    } else if (b <= 128) {
        int i = (b - 1) * 256 + tid;       // 32768 W elements
        g_Wh[i] = __float2half_rn(W[i]);
    } else {
        int i = (b - 129) * 256 + tid;
        if (i < nsrc) g_deg[i] = 0;
    }
}

// ---------------- source scores (warp per node) ----------------------------------
__global__ void score_kernel(const float* __restrict__ src, int nsrc) {
    int gtid = blockIdx.x * blockDim.x + threadIdx.x;
    int wid = gtid >> 5;
    int lane = gtid & 31;
    if (wid >= nsrc) return;
    const float* row = src + (size_t)wid * IN_F;

    float4 a = ((const float4*)row)[lane];
    float4 b = ((const float4*)row)[lane + 32];
    float4 pa = ((const float4*)g_wsproj)[lane];
    float4 pb = ((const float4*)g_wsproj)[lane + 32];
    float d = a.x * pa.x + a.y * pa.y + a.z * pa.z + a.w * pa.w
            + b.x * pb.x + b.y * pb.y + b.z * pb.z + b.w * pb.w;
#pragma unroll
    for (int o = 16; o; o >>= 1) d += __shfl_down_sync(0xFFFFFFFFu, d, o);
    if (lane == 0) g_sscore[wid] = d + g_cs;
}

// ================= wmma fp16 GEMM + fused t_score ==============================
// g_tgt_hl[M,128] = fp16( A16 @ W16^T ).  BM=64, BN=128, 256 threads (8 warps,
// warp tile 32x32), 3 CTAs/SM target for latency hiding.
#define LDT 40   // padded fp16 row pitch (80 B)

__global__ void __launch_bounds__(256, 3)
mma_gemm_kernel(const float* __restrict__ A, int M) {
    __shared__ __align__(16) char smem_raw[18944];
    __half* sA = (__half*)smem_raw;                   // 64*40*2  = 5120 B
    __half* sW = (__half*)(smem_raw + 5120);          // 128*40*2 = 10240 B

    int tid = threadIdx.x;
    int warp = tid >> 5;
    int lane = tid & 31;
    int wm = warp & 1;        // 2 warp-rows of 32
    int wn = warp >> 1;       // 4 warp-cols of 32
    int row0 = blockIdx.x * 64;

    // A-load coords: 2 float4 per thread per tile (64 rows x 32 cols fp32)
    int rq[2], cq[2], gq[2];
#pragma unroll
    for (int q = 0; q < 2; ++q) {
        int idx = tid + q * 256;          // 0..511
        rq[q] = idx >> 3;                 // 0..63
        cq[q] = (idx & 7) * 4;            // 0..28
        gq[q] = row0 + rq[q];
    }
    // W-copy coords: 2 uint4 per thread (128 rows x 32 halves = 512 uint4)
    int wrq[2], wcq[2];
#pragma unroll
    for (int q = 0; q < 2; ++q) {
        int idx = tid + q * 256;
        wrq[q] = idx >> 2;                // 0..127
        wcq[q] = (idx & 3) * 8;           // 0,8,16,24
    }

    wmma::fragment<wmma::accumulator, 16, 16, 16, float> acc[2][2];
#pragma unroll
    for (int i = 0; i < 2; ++i)
#pragma unroll
        for (int j = 0; j < 2; ++j) wmma::fill_fragment(acc[i][j], 0.f);

    float tsc[2] = {0.f, 0.f};
    float4 pva[2];
    uint4 pw[2];

    // prefetch tile k0=0
#pragma unroll
    for (int q = 0; q < 2; ++q) {
        pva[q] = make_float4(0.f, 0.f, 0.f, 0.f);
        if (gq[q] < M) pva[q] = *(const float4*)(A + (size_t)gq[q] * IN_F + cq[q]);
        pw[q] = *(const uint4*)&g_Wh[wrq[q] * IN_F + wcq[q]];
    }

    for (int k0 = 0; k0 < IN_F; k0 += 32) {
        // store current tile
#pragma unroll
        for (int q = 0; q < 2; ++q) {
            *(uint4*)&sW[wrq[q] * LDT + wcq[q]] = pw[q];
            float4 v = pva[q];
            int c4 = cq[q];
            tsc[q] += v.x * g_wtproj[k0 + c4]     + v.y * g_wtproj[k0 + c4 + 1]
                    + v.z * g_wtproj[k0 + c4 + 2] + v.w * g_wtproj[k0 + c4 + 3];
            __half2 h01 = __floats2half2_rn(v.x, v.y);
            __half2 h23 = __floats2half2_rn(v.z, v.w);
            *(uint2*)&sA[rq[q] * LDT + c4] =
                make_uint2(*(uint32_t*)&h01, *(uint32_t*)&h23);
        }
        __syncthreads();

        // prefetch next tile while MMAs run
        int kn = k0 + 32;
        if (kn < IN_F) {
#pragma unroll
            for (int q = 0; q < 2; ++q) {
                pva[q] = make_float4(0.f, 0.f, 0.f, 0.f);
                if (gq[q] < M)
                    pva[q] = *(const float4*)(A + (size_t)gq[q] * IN_F + kn + cq[q]);
                pw[q] = *(const uint4*)&g_Wh[wrq[q] * IN_F + kn + wcq[q]];
            }
        }

#pragma unroll
        for (int kf = 0; kf < 2; ++kf) {
            wmma::fragment<wmma::matrix_a, 16, 16, 16, __half,
                           wmma::row_major> af[2];
            wmma::fragment<wmma::matrix_b, 16, 16, 16, __half,
                           wmma::col_major> bf[2];
#pragma unroll
            for (int i = 0; i < 2; ++i)
                wmma::load_matrix_sync(af[i],
                    sA + (wm * 32 + i * 16) * LDT + kf * 16, LDT);
#pragma unroll
            for (int j = 0; j < 2; ++j)
                wmma::load_matrix_sync(bf[j],
                    sW + (wn * 32 + j * 16) * LDT + kf * 16, LDT);
#pragma unroll
            for (int i = 0; i < 2; ++i)
#pragma unroll
                for (int j = 0; j < 2; ++j)
                    wmma::mma_sync(acc[i][j], af[i], bf[j], acc[i][j]);
        }
        __syncthreads();
    }

    // t_score reduction: 8 consecutive lanes share one row
#pragma unroll
    for (int q = 0; q < 2; ++q) {
        float d = tsc[q];
        d += __shfl_down_sync(0xFFFFFFFFu, d, 4, 8);
        d += __shfl_down_sync(0xFFFFFFFFu, d, 2, 8);
        d += __shfl_down_sync(0xFFFFFFFFu, d, 1, 8);
        if ((tid & 7) == 0 && gq[q] < M) g_tscore[gq[q]] = d + g_ct;
    }

    // epilogue: acc -> per-warp smem stage -> fp16 global (pad covers overrun)
    float* wscr = (float*)smem_raw + warp * (16 * 36);
#pragma unroll
    for (int i = 0; i < 2; ++i) {
        __syncwarp();
        wmma::store_matrix_sync(wscr, acc[i][0], 36, wmma::mem_row_major);
        wmma::store_matrix_sync(wscr + 16, acc[i][1], 36, wmma::mem_row_major);
        __syncwarp();
        int row = lane & 15, seg = lane >> 4;
        const float* sp = wscr + row * 36 + seg * 16;
        __half2 h[8];
#pragma unroll
        for (int q = 0; q < 8; ++q)
            h[q] = __floats2half2_rn(sp[2 * q], sp[2 * q + 1]);
        size_t grow = (size_t)row0 + wm * 32 + i * 16 + row;
        __half* gp = g_tgt_hl + grow * HID + wn * 32 + seg * 16;
        *(uint4*)gp = *(uint4*)&h[0];
        *(uint4*)(gp + 8) = *(uint4*)&h[4];
    }
}

// ---------------- degree histogram (reads si only) -------------------------------
__global__ void hist_kernel(const void* __restrict__ edges, int E) {
    int i = blockIdx.x * blockDim.x + threadIdx.x;
    if (i >= E) return;
    int si = edge_at(edges, g_idx64, i);
    atomicAdd(&g_deg[si], 1);
}

// ---------------- exclusive scan of degrees --------------------------------------
__global__ void scan1_kernel(int n) {
    __shared__ int s[1024];
    int i = blockIdx.x * 1024 + threadIdx.x;
    int v = (i < n) ? g_deg[i] : 0;
    s[threadIdx.x] = v;
    __syncthreads();
#pragma unroll
    for (int o = 1; o < 1024; o <<= 1) {
        int t = (threadIdx.x >= o) ? s[threadIdx.x - o] : 0;
        __syncthreads();
        s[threadIdx.x] += t;
        __syncthreads();
    }
    if (i < n) g_base[i] = s[threadIdx.x] - v;
    if (threadIdx.x == 1023) g_bsum[blockIdx.x] = s[1023];
}
__global__ void scan2_kernel(int nb) {
    __shared__ int s[128];
    int v = (threadIdx.x < nb) ? g_bsum[threadIdx.x] : 0;
    s[threadIdx.x] = v;
    __syncthreads();
#pragma unroll
    for (int o = 1; o < 128; o <<= 1) {
        int t = (threadIdx.x >= o) ? s[threadIdx.x - o] : 0;
        __syncthreads();
        s[threadIdx.x] += t;
        __syncthreads();
    }
    if (threadIdx.x < nb) g_bsum[threadIdx.x] = s[threadIdx.x] - v;
}
__global__ void scan3_kernel(int n) {
    int i = blockIdx.x * blockDim.x + threadIdx.x;
    if (i < n) {
        int b = g_base[i] + g_bsum[i >> 10];
        g_base[i] = b;
        g_cursor[i] = b;
    }
}

// ---------------- scatter: compute ex and write (ex, ti) sorted by si ------------
// e in [-1,1] (tanh): segment-max cancels mathematically in the softmax.
__global__ void scatter_kernel(const void* __restrict__ edges, int E) {
    int i = blockIdx.x * blockDim.x + threadIdx.x;
    if (i >= E) return;
    int is64 = g_idx64;
    int si = edge_at(edges, is64, i);
    int ti = edge_at(edges, is64, (long long)E + i);
    float e = tanhf(g_sscore[si] + g_tscore[ti]);
    float ex = __expf(e);
    int pos = atomicAdd(&g_cursor[si], 1);
    g_srec[pos] = ((unsigned long long)(unsigned)__float_as_int(ex) << 32)
                | (unsigned)ti;
}

// ---------------- aggregate (warp per source node, fp16 rows) ---------------------
// out = (sum ex*v)/(sum ex) + b_lin + bias   (deg>0; else bias only)
__global__ void agg_kernel(float* __restrict__ out,
                           const float* __restrict__ bias,
                           const float* __restrict__ b_lin, int nsrc) {
    int wid = (blockIdx.x * blockDim.x + threadIdx.x) >> 5;
    int lane = threadIdx.x & 31;
    if (wid >= nsrc) return;
    int start = g_base[wid];
    int deg   = g_deg[wid];

    float4 res = ((const float4*)bias)[lane];
    if (deg > 0) {
        float4 acc = make_float4(0.f, 0.f, 0.f, 0.f);
        float denom = 0.f;
        for (int p = start; p < start + deg; ++p) {
            unsigned long long r = g_srec[p];
            int ti = (int)(unsigned)(r & 0xffffffffu);
            float ex = __int_as_float((int)(r >> 32));
            denom += ex;
            uint2 pk = ((const uint2*)(g_tgt_hl + (size_t)ti * HID))[lane];
            float2 f0 = __half22float2(*(__half2*)&pk.x);
            float2 f1 = __half22float2(*(__half2*)&pk.y);
            acc.x += ex * f0.x; acc.y += ex * f0.y;
            acc.z += ex * f1.x; acc.w += ex * f1.y;
        }
        float inv = 1.f / denom;
        float4 bl = ((const float4*)b_lin)[lane];
        res.x += bl.x + acc.x * inv; res.y += bl.y + acc.y * inv;
        res.z += bl.z + acc.z * inv; res.w += bl.w + acc.w * inv;
    }
    ((float4*)(out + (size_t)wid * HID))[lane] = res;
}

// ---------------- launch -----------------------------------------------------------
extern "C" void kernel_launch(void* const* d_in, const int* in_sizes, int n_in,
                              void* d_out, int out_size) {
    const float* source_h   = (const float*)d_in[0];
    const float* target_h   = (const float*)d_in[1];
    const void*  edges      = d_in[2];
    const float* W          = (const float*)d_in[3];
    const float* b_lin      = (const float*)d_in[4];
    const float* att_w      = (const float*)d_in[5];
    const float* att_b      = (const float*)d_in[6];
    const float* bias       = (const float*)d_in[7];

    int nsrc = in_sizes[0] / IN_F;
    int ntgt = in_sizes[1] / IN_F;
    int E    = in_sizes[2] / 2;
    float* out = (float*)d_out;
    int nb = (nsrc + 1023) / 1024;

    setup_kernel<<<129 + (nsrc + 255) / 256, 256>>>(
        W, b_lin, att_w, att_b, (const int*)edges, nsrc);
    hist_kernel<<<(E + 255) / 256, 256>>>(edges, E);
    score_kernel<<<(int)(((long long)nsrc * 32 + 255) / 256), 256>>>(
        source_h, nsrc);
    mma_gemm_kernel<<<(ntgt + 63) / 64, 256>>>(target_h, ntgt);
    scan1_kernel<<<nb, 1024>>>(nsrc);
    scan2_kernel<<<1, 128>>>(nb);
    scan3_kernel<<<(nsrc + 255) / 256, 256>>>(nsrc);
    scatter_kernel<<<(E + 255) / 256, 256>>>(edges, E);
    agg_kernel<<<(int)(((long long)nsrc * 32 + 255) / 256), 256>>>(
        out, bias, b_lin, nsrc);
}